// round 1
// baseline (speedup 1.0000x reference)
#include <cuda_runtime.h>
#include <cuda_bf16.h>
#include <math.h>

// ---------------- problem dims ----------------
#define BB   8
#define SEQ  1024
#define DM   1024
#define NH   16
#define DK   64
#define MROWS (BB*SEQ)          // 8192
#define OUT_MAIN  (BB*SEQ*DM)              // 8388608
#define OUT_ATT   (BB*NH*SEQ*SEQ)          // 134217728

// ---------------- scratch (device globals: allowed) ----------------
__device__ float g_q[BB*NH*SEQ*DK];
__device__ float g_k[BB*NH*SEQ*DK];
__device__ float g_v[BB*NH*SEQ*DK];
__device__ float g_vatt[OUT_MAIN];
__device__ float g_y[OUT_MAIN];
__device__ float g_x[OUT_MAIN];
__device__ float g_h[OUT_MAIN];
__device__ float g_w1t[DM*DM];
__device__ float g_w2t[DM*DM];
__device__ float g_att_fb[OUT_ATT];   // fallback if out buffer lacks att region

// ---------------- fast exp (FMA-only, avoids MUFU bottleneck) ----------------
__device__ __forceinline__ float fast_exp(float x) {
    if (x < -87.0f) return 0.0f;
    float t  = x * 1.4426950408889634f;   // log2(e)
    float fi = floorf(t);
    float f  = t - fi;                    // [0,1)
    float p  = 1.5403530e-4f;
    p = fmaf(p, f, 1.3333558e-3f);
    p = fmaf(p, f, 9.6181291e-3f);
    p = fmaf(p, f, 5.5504109e-2f);
    p = fmaf(p, f, 2.4022651e-1f);
    p = fmaf(p, f, 6.9314718e-1f);
    p = fmaf(p, f, 1.0f);
    return __int_as_float(((int)fi + 127) << 23) * p;
}

// ---------------- transpose 1024x1024 ----------------
__global__ void transpose1024(const float* __restrict__ in, float* __restrict__ out) {
    __shared__ float t[32][33];
    const int bx = blockIdx.x * 32, by = blockIdx.y * 32;
    const int txx = threadIdx.x, tyy = threadIdx.y;
#pragma unroll
    for (int j = 0; j < 32; j += 8)
        t[tyy + j][txx] = in[(by + tyy + j) * 1024 + bx + txx];
    __syncthreads();
#pragma unroll
    for (int j = 0; j < 32; j += 8)
        out[(bx + tyy + j) * 1024 + by + txx] = t[txx][tyy + j];
}

// ---------------- sgemm 128x128x8, 8x8 per thread ----------------
// C[8192,1024] = A[8192,1024] * B[1024,1024], fused epilogues.
// MODE 0: scatter to q/k/v layout [B,H,S,64]
// MODE 1: C = AB + res            (W_o + residual Q)
// MODE 2: C = gelu(AB + bias)     (FFN1)
// MODE 3: C = AB + bias + res     (FFN2)
template<int MODE>
__global__ void __launch_bounds__(256) sgemm_k(
    const float* __restrict__ A, const float* __restrict__ Bm,
    float* __restrict__ C, const float* __restrict__ res,
    const float* __restrict__ bias)
{
    constexpr int N = 1024, K = 1024;
    __shared__ float As[8][128];
    __shared__ float Bs[8][128];
    const int tid = threadIdx.x;
    const int m0 = blockIdx.y * 128, n0 = blockIdx.x * 128;

    const int arow = tid >> 1, akq = (tid & 1) * 4;
    const int brow = tid >> 5, bcol = (tid & 31) * 4;
    const float* aptr = A  + (m0 + arow) * K + akq;
    const float* bptr = Bm + brow * N + n0 + bcol;

    float4 a4 = *(const float4*)aptr;
    float4 b4 = *(const float4*)bptr;

    const int ty = tid >> 4, tx = tid & 15;
    float acc[8][8];
#pragma unroll
    for (int i = 0; i < 8; i++)
#pragma unroll
        for (int j = 0; j < 8; j++) acc[i][j] = 0.0f;

    for (int t = 0; t < K / 8; t++) {
        As[akq + 0][arow] = a4.x;
        As[akq + 1][arow] = a4.y;
        As[akq + 2][arow] = a4.z;
        As[akq + 3][arow] = a4.w;
        *(float4*)&Bs[brow][bcol] = b4;
        __syncthreads();
        if (t < K / 8 - 1) {
            a4 = *(const float4*)(aptr + (t + 1) * 8);
            b4 = *(const float4*)(bptr + (t + 1) * 8 * N);
        }
#pragma unroll
        for (int kk = 0; kk < 8; kk++) {
            float4 av0 = *(const float4*)&As[kk][ty * 8];
            float4 av1 = *(const float4*)&As[kk][ty * 8 + 4];
            float4 bv0 = *(const float4*)&Bs[kk][tx * 8];
            float4 bv1 = *(const float4*)&Bs[kk][tx * 8 + 4];
            float ar[8] = {av0.x, av0.y, av0.z, av0.w, av1.x, av1.y, av1.z, av1.w};
            float br[8] = {bv0.x, bv0.y, bv0.z, bv0.w, bv1.x, bv1.y, bv1.z, bv1.w};
#pragma unroll
            for (int i = 0; i < 8; i++)
#pragma unroll
                for (int j = 0; j < 8; j++)
                    acc[i][j] = fmaf(ar[i], br[j], acc[i][j]);
        }
        __syncthreads();
    }

    // epilogue
#pragma unroll
    for (int i = 0; i < 8; i++) {
        const int m = m0 + ty * 8 + i;
#pragma unroll
        for (int jj = 0; jj < 2; jj++) {
            const int n = n0 + tx * 8 + jj * 4;
            float4 v;
            v.x = acc[i][jj * 4 + 0];
            v.y = acc[i][jj * 4 + 1];
            v.z = acc[i][jj * 4 + 2];
            v.w = acc[i][jj * 4 + 3];
            if (MODE == 0) {
                const int b = m >> 10, s = m & 1023, h = n >> 6, d = n & 63;
                float* dst = C + ((long)((b * 16 + h) * 1024 + s)) * 64 + d;
                *(float4*)dst = v;
            } else if (MODE == 1) {
                const float4 r4 = *(const float4*)&res[(long)m * N + n];
                v.x += r4.x; v.y += r4.y; v.z += r4.z; v.w += r4.w;
                *(float4*)&C[(long)m * N + n] = v;
            } else if (MODE == 2) {
                const float4 bi = *(const float4*)&bias[n];
                float x0 = v.x + bi.x, x1 = v.y + bi.y, x2 = v.z + bi.z, x3 = v.w + bi.w;
                const float is2 = 0.70710678118654752f;
                v.x = 0.5f * x0 * (1.0f + erff(x0 * is2));
                v.y = 0.5f * x1 * (1.0f + erff(x1 * is2));
                v.z = 0.5f * x2 * (1.0f + erff(x2 * is2));
                v.w = 0.5f * x3 * (1.0f + erff(x3 * is2));
                *(float4*)&C[(long)m * N + n] = v;
            } else {
                const float4 bi = *(const float4*)&bias[n];
                const float4 r4 = *(const float4*)&res[(long)m * N + n];
                v.x += bi.x + r4.x; v.y += bi.y + r4.y;
                v.z += bi.z + r4.z; v.w += bi.w + r4.w;
                *(float4*)&C[(long)m * N + n] = v;
            }
        }
    }
}

// ---------------- fused attention ----------------
// One block = one (bh, 32-row q tile). Scores -> shared, softmax, att write, AV.
#define QT 32
#define SSTR 1028
constexpr int SMEM_ATTN = (64 * 33 + 64 * 68 + 64 * 68 + QT * SSTR) * 4;

__global__ void __launch_bounds__(256) attn_kernel(
    const float* __restrict__ qb, const float* __restrict__ kb,
    const float* __restrict__ vb, const unsigned char* __restrict__ mask,
    float* __restrict__ att, float* __restrict__ vatt)
{
    extern __shared__ float sh[];
    float* Qs = sh;                       // [64 d][33]  (d-major, rows 0..31)
    float* Ks = Qs + 64 * 33;             // [64 d][68]  (d-major, cols 0..63)
    float* Vs = Ks + 64 * 68;             // [64 k][68]  (k-major)
    float* Ss = Vs + 64 * 68;             // [32][1028]
    __shared__ int s_anymask;

    const int tid = threadIdx.x;
    const int qt = blockIdx.x;
    const int bh = blockIdx.y;
    const int b  = bh >> 4;
    const int q0 = qt * QT;
    const long basehd = (long)bh * SEQ * DK;

    // load Q tile transposed
    for (int i = tid; i < QT * 64; i += 256) {
        const int r = i >> 6, d = i & 63;
        Qs[d * 33 + r] = qb[basehd + (long)(q0 + r) * 64 + d];
    }
    if (tid == 0) s_anymask = 0;
    __syncthreads();
    if (tid < QT && mask[b * SEQ + q0 + tid]) s_anymask = 1;

    const int kt_max = (q0 + QT - 1) >> 6;
    const float scale = 1.0f / (8.0f + 1e-6f);

    // ---- scores ----
    const int sty = tid >> 4, stx = tid & 15;
    const int r0 = sty * 2, c0 = stx * 4;
    for (int kt = 0; kt <= kt_max; kt++) {
        __syncthreads();
        for (int i = tid; i < 64 * 64; i += 256) {
            const int c = i >> 6, d = i & 63;
            Ks[d * 68 + c] = kb[basehd + (long)(kt * 64 + c) * 64 + d];
        }
        __syncthreads();
        float a00 = 0, a01 = 0, a02 = 0, a03 = 0;
        float a10 = 0, a11 = 0, a12 = 0, a13 = 0;
#pragma unroll 16
        for (int kk = 0; kk < 64; kk++) {
            const float q0v = Qs[kk * 33 + r0];
            const float q1v = Qs[kk * 33 + r0 + 1];
            const float4 kv = *(const float4*)&Ks[kk * 68 + c0];
            a00 = fmaf(q0v, kv.x, a00); a01 = fmaf(q0v, kv.y, a01);
            a02 = fmaf(q0v, kv.z, a02); a03 = fmaf(q0v, kv.w, a03);
            a10 = fmaf(q1v, kv.x, a10); a11 = fmaf(q1v, kv.y, a11);
            a12 = fmaf(q1v, kv.z, a12); a13 = fmaf(q1v, kv.w, a13);
        }
        float* s0 = &Ss[r0 * SSTR + kt * 64 + c0];
        float* s1 = &Ss[(r0 + 1) * SSTR + kt * 64 + c0];
        s0[0] = a00 * scale; s0[1] = a01 * scale; s0[2] = a02 * scale; s0[3] = a03 * scale;
        s1[0] = a10 * scale; s1[1] = a11 * scale; s1[2] = a12 * scale; s1[3] = a13 * scale;
    }
    __syncthreads();

    // ---- softmax (8 threads per row) ----
    const int r  = tid >> 3, tc = tid & 7;
    const int qg = q0 + r;
    const int limit = qg;
    const bool rmask = mask[b * SEQ + qg] != 0;
    float* srow = &Ss[r * SSTR];

    float mx = -3.4e38f;
    for (int j = 0; j < 128; j++) {
        const int k = tc + (j << 3);
        if (k <= limit) mx = fmaxf(mx, srow[k]);
    }
#pragma unroll
    for (int off = 4; off; off >>= 1)
        mx = fmaxf(mx, __shfl_xor_sync(0xffffffffu, mx, off, 8));

    float l = 0.0f;
    for (int j = 0; j < 128; j++) {
        const int k = tc + (j << 3);
        if (k <= limit) {
            const float e = fast_exp(srow[k] - mx);
            srow[k] = e;
            l += e;
        }
    }
#pragma unroll
    for (int off = 4; off; off >>= 1)
        l += __shfl_xor_sync(0xffffffffu, l, off, 8);
    const float inv = 1.0f / l;

    float* attrow = att + ((long)bh * SEQ + qg) * SEQ;
    const float invS = 1.0f / (float)SEQ;
    for (int j = 0; j < 128; j++) {
        const int k = tc + (j << 3);
        float p;
        if (rmask)            p = invS;
        else if (k <= limit)  p = srow[k] * inv;
        else                  p = 0.0f;
        srow[k] = p;
        attrow[k] = p;
    }
    __syncthreads();

    // ---- AV ----
    const int d0 = tc * 8;
    float acc[8] = {0, 0, 0, 0, 0, 0, 0, 0};
    const int kt_end = s_anymask ? (SEQ / 64 - 1) : kt_max;
    for (int kt = 0; kt <= kt_end; kt++) {
        __syncthreads();
        for (int i = tid; i < 64 * 64; i += 256) {
            const int c = i >> 6, d = i & 63;
            Vs[c * 68 + d] = vb[basehd + (long)(kt * 64 + c) * 64 + d];
        }
        __syncthreads();
#pragma unroll 8
        for (int k = 0; k < 64; k++) {
            const float p = srow[kt * 64 + k];
            const float4 v0 = *(const float4*)&Vs[k * 68 + d0];
            const float4 v1 = *(const float4*)&Vs[k * 68 + d0 + 4];
            acc[0] = fmaf(p, v0.x, acc[0]); acc[1] = fmaf(p, v0.y, acc[1]);
            acc[2] = fmaf(p, v0.z, acc[2]); acc[3] = fmaf(p, v0.w, acc[3]);
            acc[4] = fmaf(p, v1.x, acc[4]); acc[5] = fmaf(p, v1.y, acc[5]);
            acc[6] = fmaf(p, v1.z, acc[6]); acc[7] = fmaf(p, v1.w, acc[7]);
        }
    }
    const int h = bh & 15;
    float* orow = vatt + ((long)(b * SEQ + qg)) * DM + h * 64 + d0;
    float4 o0, o1;
    o0.x = acc[0]; o0.y = acc[1]; o0.z = acc[2]; o0.w = acc[3];
    o1.x = acc[4]; o1.y = acc[5]; o1.z = acc[6]; o1.w = acc[7];
    *(float4*)orow = o0;
    *(float4*)(orow + 4) = o1;
}

// ---------------- layernorm over rows of 1024 ----------------
__global__ void __launch_bounds__(256) ln_kernel(
    const float* __restrict__ x, const float* __restrict__ gam,
    const float* __restrict__ bet, float* __restrict__ out)
{
    __shared__ float red[256];
    const int row = blockIdx.x, tid = threadIdx.x;
    const float4 v = ((const float4*)x)[(long)row * 256 + tid];
    red[tid] = v.x + v.y + v.z + v.w;
    __syncthreads();
#pragma unroll
    for (int off = 128; off; off >>= 1) {
        if (tid < off) red[tid] += red[tid + off];
        __syncthreads();
    }
    const float mu = red[0] * (1.0f / 1024.0f);
    __syncthreads();
    const float dx = v.x - mu, dy = v.y - mu, dz = v.z - mu, dw = v.w - mu;
    red[tid] = dx * dx + dy * dy + dz * dz + dw * dw;
    __syncthreads();
#pragma unroll
    for (int off = 128; off; off >>= 1) {
        if (tid < off) red[tid] += red[tid + off];
        __syncthreads();
    }
    const float var = red[0] * (1.0f / 1024.0f);
    const float rs = rsqrtf(var + 1e-5f);
    const float4 g4 = ((const float4*)gam)[tid];
    const float4 b4 = ((const float4*)bet)[tid];
    float4 o;
    o.x = g4.x * dx * rs + b4.x;
    o.y = g4.y * dy * rs + b4.y;
    o.z = g4.z * dz * rs + b4.z;
    o.w = g4.w * dw * rs + b4.w;
    ((float4*)out)[(long)row * 256 + tid] = o;
}

// ---------------- launch ----------------
extern "C" void kernel_launch(void* const* d_in, const int* in_sizes, int n_in,
                              void* d_out, int out_size) {
    const float* Qin  = (const float*)d_in[0];
    const float* Kin  = (const float*)d_in[1];
    const float* Vin  = (const float*)d_in[2];
    const unsigned char* mask = (const unsigned char*)d_in[3];
    const float* W_q  = (const float*)d_in[4];
    const float* W_k  = (const float*)d_in[5];
    const float* W_v  = (const float*)d_in[6];
    const float* W_o  = (const float*)d_in[7];
    const float* w1   = (const float*)d_in[8];
    const float* b1   = (const float*)d_in[9];
    const float* w2   = (const float*)d_in[10];
    const float* b2   = (const float*)d_in[11];
    const float* ln_g = (const float*)d_in[12];
    const float* ln_b = (const float*)d_in[13];

    float *q_, *k_, *v_, *vatt_, *y_, *x_, *h_, *w1t_, *w2t_, *attfb_;
    cudaGetSymbolAddress((void**)&q_,    g_q);
    cudaGetSymbolAddress((void**)&k_,    g_k);
    cudaGetSymbolAddress((void**)&v_,    g_v);
    cudaGetSymbolAddress((void**)&vatt_, g_vatt);
    cudaGetSymbolAddress((void**)&y_,    g_y);
    cudaGetSymbolAddress((void**)&x_,    g_x);
    cudaGetSymbolAddress((void**)&h_,    g_h);
    cudaGetSymbolAddress((void**)&w1t_,  g_w1t);
    cudaGetSymbolAddress((void**)&w2t_,  g_w2t);
    cudaGetSymbolAddress((void**)&attfb_, g_att_fb);

    float* out = (float*)d_out;
    float* att = (out_size >= (int)(OUT_MAIN + OUT_ATT)) ? (out + OUT_MAIN) : attfb_;

    // weight transposes for FFN (X @ w^T -> NN gemm)
    transpose1024<<<dim3(32, 32), dim3(32, 8)>>>(w1, w1t_);
    transpose1024<<<dim3(32, 32), dim3(32, 8)>>>(w2, w2t_);

    const dim3 gG(8, 64), bG(256);
    sgemm_k<0><<<gG, bG>>>(Qin, W_q, q_, nullptr, nullptr);
    sgemm_k<0><<<gG, bG>>>(Kin, W_k, k_, nullptr, nullptr);
    sgemm_k<0><<<gG, bG>>>(Vin, W_v, v_, nullptr, nullptr);

    cudaFuncSetAttribute(attn_kernel, cudaFuncAttributeMaxDynamicSharedMemorySize, SMEM_ATTN);
    attn_kernel<<<dim3(SEQ / QT, BB * NH), 256, SMEM_ATTN>>>(q_, k_, v_, mask, att, vatt_);

    sgemm_k<1><<<gG, bG>>>(vatt_, W_o, y_, Qin, nullptr);      // + residual Q
    ln_kernel<<<MROWS, 256>>>(y_, ln_g, ln_b, x_);             // X
    sgemm_k<2><<<gG, bG>>>(x_, w1t_, h_, nullptr, b1);         // gelu(X w1^T + b1)
    sgemm_k<3><<<gG, bG>>>(h_, w2t_, y_, x_, b2);              // h w2^T + b2 + X
    ln_kernel<<<MROWS, 256>>>(y_, ln_g, ln_b, out);            // output
}

// round 5
// speedup vs baseline: 1.3782x; 1.3782x over previous
#include <cuda_runtime.h>
#include <cuda_bf16.h>
#include <math.h>
#include <stdint.h>

// ---------------- problem dims ----------------
#define BB   8
#define SEQ  1024
#define DM   1024
#define NH   16
#define DK   64
#define MROWS (BB*SEQ)          // 8192
#define OUT_MAIN  (BB*SEQ*DM)              // 8388608
#define OUT_ATT   (BB*NH*SEQ*SEQ)          // 134217728

// ---------------- scratch ----------------
__device__ float g_q[BB*NH*SEQ*DK];
__device__ float g_k[BB*NH*SEQ*DK];
__device__ float g_v[BB*NH*SEQ*DK];
__device__ float g_vatt[OUT_MAIN];
__device__ float g_y[OUT_MAIN];
__device__ float g_x[OUT_MAIN];
__device__ float g_h[OUT_MAIN];
__device__ float g_att_fb[OUT_ATT];

__device__ __align__(128) __nv_bfloat16 g_ahi[MROWS*DM];
__device__ __align__(128) __nv_bfloat16 g_alo[MROWS*DM];
__device__ __align__(128) __nv_bfloat16 g_wqh[DM*DM], g_wql[DM*DM];
__device__ __align__(128) __nv_bfloat16 g_wkh[DM*DM], g_wkl[DM*DM];
__device__ __align__(128) __nv_bfloat16 g_wvh[DM*DM], g_wvl[DM*DM];
__device__ __align__(128) __nv_bfloat16 g_woh[DM*DM], g_wol[DM*DM];
__device__ __align__(128) __nv_bfloat16 g_w1h[DM*DM], g_w1l[DM*DM];
__device__ __align__(128) __nv_bfloat16 g_w2h[DM*DM], g_w2l[DM*DM];

// ---------------- helpers ----------------
__device__ __forceinline__ uint32_t cvta_s(const void* p) {
    return (uint32_t)__cvta_generic_to_shared(p);
}
__device__ __forceinline__ void ldsm4(uint32_t r[4], uint32_t a) {
    asm volatile("ldmatrix.sync.aligned.m8n8.x4.shared.b16 {%0,%1,%2,%3}, [%4];"
                 : "=r"(r[0]), "=r"(r[1]), "=r"(r[2]), "=r"(r[3]) : "r"(a));
}
__device__ __forceinline__ void ldsm2(uint32_t r[2], uint32_t a) {
    asm volatile("ldmatrix.sync.aligned.m8n8.x2.shared.b16 {%0,%1}, [%2];"
                 : "=r"(r[0]), "=r"(r[1]) : "r"(a));
}
__device__ __forceinline__ void mma_bf16(float c[4], const uint32_t a[4], const uint32_t b[2]) {
    asm volatile(
        "mma.sync.aligned.m16n8k16.row.col.f32.bf16.bf16.f32 "
        "{%0,%1,%2,%3}, {%4,%5,%6,%7}, {%8,%9}, {%0,%1,%2,%3};"
        : "+f"(c[0]), "+f"(c[1]), "+f"(c[2]), "+f"(c[3])
        : "r"(a[0]), "r"(a[1]), "r"(a[2]), "r"(a[3]), "r"(b[0]), "r"(b[1]));
}
__device__ __forceinline__ void cp16(uint32_t d, const void* g) {
    asm volatile("cp.async.cg.shared.global [%0], [%1], 16;" :: "r"(d), "l"(g));
}
#define CP_COMMIT() asm volatile("cp.async.commit_group;" ::: "memory")

// ---------------- fast exp (FMA-only) ----------------
__device__ __forceinline__ float fast_exp(float x) {
    if (x < -87.0f) return 0.0f;
    float t  = x * 1.4426950408889634f;
    float fi = floorf(t);
    float f  = t - fi;
    float p  = 1.5403530e-4f;
    p = fmaf(p, f, 1.3333558e-3f);
    p = fmaf(p, f, 9.6181291e-3f);
    p = fmaf(p, f, 5.5504109e-2f);
    p = fmaf(p, f, 2.4022651e-1f);
    p = fmaf(p, f, 6.9314718e-1f);
    p = fmaf(p, f, 1.0f);
    return __int_as_float(((int)fi + 127) << 23) * p;
}

// ---------------- bf16 split kernels ----------------
__global__ void __launch_bounds__(256) split_kernel(
    const float* __restrict__ in, __nv_bfloat16* __restrict__ hi,
    __nv_bfloat16* __restrict__ lo)
{
    const int i = blockIdx.x * 256 + threadIdx.x;
    const float4 v = ((const float4*)in)[i];
    __nv_bfloat16 h0 = __float2bfloat16(v.x);
    __nv_bfloat16 h1 = __float2bfloat16(v.y);
    __nv_bfloat16 h2 = __float2bfloat16(v.z);
    __nv_bfloat16 h3 = __float2bfloat16(v.w);
    __nv_bfloat16 l0 = __float2bfloat16(v.x - __bfloat162float(h0));
    __nv_bfloat16 l1 = __float2bfloat16(v.y - __bfloat162float(h1));
    __nv_bfloat16 l2 = __float2bfloat16(v.z - __bfloat162float(h2));
    __nv_bfloat16 l3 = __float2bfloat16(v.w - __bfloat162float(h3));
    __nv_bfloat162 hp0; hp0.x = h0; hp0.y = h1;
    __nv_bfloat162 hp1; hp1.x = h2; hp1.y = h3;
    __nv_bfloat162 lp0; lp0.x = l0; lp0.y = l1;
    __nv_bfloat162 lp1; lp1.x = l2; lp1.y = l3;
    ((__nv_bfloat162*)hi)[i*2]   = hp0;
    ((__nv_bfloat162*)hi)[i*2+1] = hp1;
    ((__nv_bfloat162*)lo)[i*2]   = lp0;
    ((__nv_bfloat162*)lo)[i*2+1] = lp1;
}

// weights [K][N] -> split transposed [N][K]
__global__ void __launch_bounds__(256) split_transpose(
    const float* __restrict__ in, __nv_bfloat16* __restrict__ hi,
    __nv_bfloat16* __restrict__ lo)
{
    __shared__ float t[32][33];
    const int bx = blockIdx.x * 32, by = blockIdx.y * 32;
    const int txx = threadIdx.x, tyy = threadIdx.y;
#pragma unroll
    for (int j = 0; j < 32; j += 8)
        t[tyy + j][txx] = in[(by + tyy + j) * 1024 + bx + txx];
    __syncthreads();
#pragma unroll
    for (int j = 0; j < 32; j += 8) {
        const float v = t[txx][tyy + j];
        __nv_bfloat16 h = __float2bfloat16(v);
        __nv_bfloat16 l = __float2bfloat16(v - __bfloat162float(h));
        const int idx = (bx + tyy + j) * 1024 + by + txx;
        hi[idx] = h;
        lo[idx] = l;
    }
}

// ---------------- HMMA bf16x3 GEMM ----------------
// C[8192,1024] = A * B^T, A split (Ahi,Alo)[M][K], B split (Bhi,Blo)[N][K].
// Tile 128x128, K-chunk 32, double buffered. 8 warps = 2(M) x 4(N), warp tile 64x32.
// smem per stage: 4 arrays of 128 rows x 40 bf16 (80B padded) = 40960 B.
#define ROWB 80
#define ASTG 10240
#define STG  40960
#define GEMM_SMEM (2 * STG)

template<int MODE>
__global__ void __launch_bounds__(256) mma_gemm(
    const __nv_bfloat16* __restrict__ Ahi, const __nv_bfloat16* __restrict__ Alo,
    const __nv_bfloat16* __restrict__ Bhi, const __nv_bfloat16* __restrict__ Blo,
    float* __restrict__ C, const float* __restrict__ res, const float* __restrict__ bias)
{
    extern __shared__ __align__(128) char smem[];
    const int tid = threadIdx.x;
    const int lane = tid & 31, w = tid >> 5;
    const int wm = w >> 2, wn = w & 3;
    const int m0 = blockIdx.y * 128, n0 = blockIdx.x * 128;
    const uint32_t sbase = cvta_s(smem);

    float acc[4][4][4];
#pragma unroll
    for (int i = 0; i < 4; i++)
#pragma unroll
        for (int j = 0; j < 4; j++)
#pragma unroll
            for (int k = 0; k < 4; k++) acc[i][j][k] = 0.0f;

    const __nv_bfloat16* gsrc[4] = {Ahi, Alo, Bhi, Blo};

    auto fill = [&](int buf, int kc) {
        const int k0 = kc * 32;
        const uint32_t dst0 = sbase + buf * STG;
#pragma unroll
        for (int i = 0; i < 8; i++) {
            const int idx = i * 256 + tid;         // 0..2047
            const int arr = idx >> 9;              // 0..3
            const int within = idx & 511;
            const int row = within >> 2, seg = within & 3;
            const int grow = (arr < 2 ? m0 : n0) + row;
            const __nv_bfloat16* g = gsrc[arr] + (long)grow * 1024 + k0 + seg * 8;
            cp16(dst0 + arr * ASTG + row * ROWB + seg * 16, g);
        }
        CP_COMMIT();
    };

    fill(0, 0);
    for (int c = 0; c < 32; c++) {
        const int buf = c & 1;
        if (c + 1 < 32) {
            fill(buf ^ 1, c + 1);
            asm volatile("cp.async.wait_group 1;" ::: "memory");
        } else {
            asm volatile("cp.async.wait_group 0;" ::: "memory");
        }
        __syncthreads();

        const uint32_t sb = sbase + buf * STG;
#pragma unroll
        for (int s = 0; s < 2; s++) {
            uint32_t ah[4][4], al[4][4], bh[4][2], bl[4][2];
            const int acol = (s * 16 + (lane >> 4) * 8) * 2;
            const int arow = lane & 15;
#pragma unroll
            for (int mt = 0; mt < 4; mt++) {
                const uint32_t ao = sb + (wm * 64 + mt * 16 + arow) * ROWB + acol;
                ldsm4(ah[mt], ao);
                ldsm4(al[mt], ao + ASTG);
            }
            const int le = lane & 15;
            const int bcol = (s * 16 + ((le >> 3) & 1) * 8) * 2;
            const int brow = le & 7;
#pragma unroll
            for (int nt = 0; nt < 4; nt++) {
                const uint32_t bo = sb + 2 * ASTG + (wn * 32 + nt * 8 + brow) * ROWB + bcol;
                ldsm2(bh[nt], bo);
                ldsm2(bl[nt], bo + ASTG);
            }
#pragma unroll
            for (int mt = 0; mt < 4; mt++)
#pragma unroll
                for (int nt = 0; nt < 4; nt++) {
                    mma_bf16(acc[mt][nt], ah[mt], bh[nt]);
                    mma_bf16(acc[mt][nt], ah[mt], bl[nt]);
                    mma_bf16(acc[mt][nt], al[mt], bh[nt]);
                }
        }
        __syncthreads();
    }

    // ---- epilogue ----
    const int g = lane >> 2, t4 = lane & 3;
#pragma unroll
    for (int mt = 0; mt < 4; mt++) {
#pragma unroll
        for (int half = 0; half < 2; half++) {
            const int m = m0 + wm * 64 + mt * 16 + g + half * 8;
#pragma unroll
            for (int nt = 0; nt < 4; nt++) {
                const int n = n0 + wn * 32 + nt * 8 + t4 * 2;
                float v0 = acc[mt][nt][half * 2 + 0];
                float v1 = acc[mt][nt][half * 2 + 1];
                if (MODE == 0) {
                    const int b = m >> 10, s = m & 1023, h = n >> 6, d = n & 63;
                    float* dst = C + ((long)((b * 16 + h) * 1024 + s)) * 64 + d;
                    float2 o; o.x = v0; o.y = v1;
                    *(float2*)dst = o;
                } else if (MODE == 1) {
                    const float2 r2 = *(const float2*)&res[(long)m * 1024 + n];
                    float2 o; o.x = v0 + r2.x; o.y = v1 + r2.y;
                    *(float2*)&C[(long)m * 1024 + n] = o;
                } else if (MODE == 2) {
                    const float2 bi = *(const float2*)&bias[n];
                    const float is2 = 0.70710678118654752f;
                    float x0 = v0 + bi.x, x1 = v1 + bi.y;
                    float2 o;
                    o.x = 0.5f * x0 * (1.0f + erff(x0 * is2));
                    o.y = 0.5f * x1 * (1.0f + erff(x1 * is2));
                    *(float2*)&C[(long)m * 1024 + n] = o;
                } else {
                    const float2 bi = *(const float2*)&bias[n];
                    const float2 r2 = *(const float2*)&res[(long)m * 1024 + n];
                    float2 o; o.x = v0 + bi.x + r2.x; o.y = v1 + bi.y + r2.y;
                    *(float2*)&C[(long)m * 1024 + n] = o;
                }
            }
        }
    }
}

// ---------------- fused attention (fp32) ----------------
#define QT 32
#define SSTR 1028
constexpr int SMEM_ATTN = (64 * 33 + 64 * 68 + 64 * 68 + QT * SSTR) * 4;

__global__ void __launch_bounds__(256) attn_kernel(
    const float* __restrict__ qb, const float* __restrict__ kb,
    const float* __restrict__ vb, const unsigned char* __restrict__ mask,
    float* __restrict__ att, float* __restrict__ vatt)
{
    extern __shared__ float sh[];
    float* Qs = sh;
    float* Ks = Qs + 64 * 33;
    float* Vs = Ks + 64 * 68;
    float* Ss = Vs + 64 * 68;
    __shared__ int s_anymask;

    const int tid = threadIdx.x;
    const int qt = blockIdx.x;
    const int bh = blockIdx.y;
    const int b  = bh >> 4;
    const int q0 = qt * QT;
    const long basehd = (long)bh * SEQ * DK;

    for (int i = tid; i < QT * 64; i += 256) {
        const int r = i >> 6, d = i & 63;
        Qs[d * 33 + r] = qb[basehd + (long)(q0 + r) * 64 + d];
    }
    if (tid == 0) s_anymask = 0;
    __syncthreads();
    if (tid < QT && mask[b * SEQ + q0 + tid]) s_anymask = 1;

    const int kt_max = (q0 + QT - 1) >> 6;
    const float scale = 1.0f / (8.0f + 1e-6f);

    const int sty = tid >> 4, stx = tid & 15;
    const int r0 = sty * 2, c0 = stx * 4;
    for (int kt = 0; kt <= kt_max; kt++) {
        __syncthreads();
        for (int i = tid; i < 64 * 64; i += 256) {
            const int c = i >> 6, d = i & 63;
            Ks[d * 68 + c] = kb[basehd + (long)(kt * 64 + c) * 64 + d];
        }
        __syncthreads();
        float a00 = 0, a01 = 0, a02 = 0, a03 = 0;
        float a10 = 0, a11 = 0, a12 = 0, a13 = 0;
#pragma unroll 16
        for (int kk = 0; kk < 64; kk++) {
            const float q0v = Qs[kk * 33 + r0];
            const float q1v = Qs[kk * 33 + r0 + 1];
            const float4 kv = *(const float4*)&Ks[kk * 68 + c0];
            a00 = fmaf(q0v, kv.x, a00); a01 = fmaf(q0v, kv.y, a01);
            a02 = fmaf(q0v, kv.z, a02); a03 = fmaf(q0v, kv.w, a03);
            a10 = fmaf(q1v, kv.x, a10); a11 = fmaf(q1v, kv.y, a11);
            a12 = fmaf(q1v, kv.z, a12); a13 = fmaf(q1v, kv.w, a13);
        }
        float* s0 = &Ss[r0 * SSTR + kt * 64 + c0];
        float* s1 = &Ss[(r0 + 1) * SSTR + kt * 64 + c0];
        s0[0] = a00 * scale; s0[1] = a01 * scale; s0[2] = a02 * scale; s0[3] = a03 * scale;
        s1[0] = a10 * scale; s1[1] = a11 * scale; s1[2] = a12 * scale; s1[3] = a13 * scale;
    }
    __syncthreads();

    const int r  = tid >> 3, tc = tid & 7;
    const int qg = q0 + r;
    const int limit = qg;
    const bool rmask = mask[b * SEQ + qg] != 0;
    float* srow = &Ss[r * SSTR];

    float mx = -3.4e38f;
    for (int j = 0; j < 128; j++) {
        const int k = tc + (j << 3);
        if (k <= limit) mx = fmaxf(mx, srow[k]);
    }
#pragma unroll
    for (int off = 4; off; off >>= 1)
        mx = fmaxf(mx, __shfl_xor_sync(0xffffffffu, mx, off, 8));

    float l = 0.0f;
    for (int j = 0; j < 128; j++) {
        const int k = tc + (j << 3);
        if (k <= limit) {
            const float e = fast_exp(srow[k] - mx);
            srow[k] = e;
            l += e;
        }
    }
#pragma unroll
    for (int off = 4; off; off >>= 1)
        l += __shfl_xor_sync(0xffffffffu, l, off, 8);
    const float inv = 1.0f / l;

    float* attrow = att + ((long)bh * SEQ + qg) * SEQ;
    const float invS = 1.0f / (float)SEQ;
    for (int j = 0; j < 128; j++) {
        const int k = tc + (j << 3);
        float p;
        if (rmask)            p = invS;
        else if (k <= limit)  p = srow[k] * inv;
        else                  p = 0.0f;
        srow[k] = p;
        attrow[k] = p;
    }
    __syncthreads();

    const int d0 = tc * 8;
    float acc[8] = {0, 0, 0, 0, 0, 0, 0, 0};
    const int kt_end = s_anymask ? (SEQ / 64 - 1) : kt_max;
    for (int kt = 0; kt <= kt_end; kt++) {
        __syncthreads();
        for (int i = tid; i < 64 * 64; i += 256) {
            const int c = i >> 6, d = i & 63;
            Vs[c * 68 + d] = vb[basehd + (long)(kt * 64 + c) * 64 + d];
        }
        __syncthreads();
#pragma unroll 8
        for (int k = 0; k < 64; k++) {
            const float p = srow[kt * 64 + k];
            const float4 v0 = *(const float4*)&Vs[k * 68 + d0];
            const float4 v1 = *(const float4*)&Vs[k * 68 + d0 + 4];
            acc[0] = fmaf(p, v0.x, acc[0]); acc[1] = fmaf(p, v0.y, acc[1]);
            acc[2] = fmaf(p, v0.z, acc[2]); acc[3] = fmaf(p, v0.w, acc[3]);
            acc[4] = fmaf(p, v1.x, acc[4]); acc[5] = fmaf(p, v1.y, acc[5]);
            acc[6] = fmaf(p, v1.z, acc[6]); acc[7] = fmaf(p, v1.w, acc[7]);
        }
    }
    const int h = bh & 15;
    float* orow = vatt + ((long)(b * SEQ + qg)) * DM + h * 64 + d0;
    float4 o0, o1;
    o0.x = acc[0]; o0.y = acc[1]; o0.z = acc[2]; o0.w = acc[3];
    o1.x = acc[4]; o1.y = acc[5]; o1.z = acc[6]; o1.w = acc[7];
    *(float4*)orow = o0;
    *(float4*)(orow + 4) = o1;
}

// ---------------- layernorm ----------------
__global__ void __launch_bounds__(256) ln_kernel(
    const float* __restrict__ x, const float* __restrict__ gam,
    const float* __restrict__ bet, float* __restrict__ out)
{
    __shared__ float red[256];
    const int row = blockIdx.x, tid = threadIdx.x;
    const float4 v = ((const float4*)x)[(long)row * 256 + tid];
    red[tid] = v.x + v.y + v.z + v.w;
    __syncthreads();
#pragma unroll
    for (int off = 128; off; off >>= 1) {
        if (tid < off) red[tid] += red[tid + off];
        __syncthreads();
    }
    const float mu = red[0] * (1.0f / 1024.0f);
    __syncthreads();
    const float dx = v.x - mu, dy = v.y - mu, dz = v.z - mu, dw = v.w - mu;
    red[tid] = dx * dx + dy * dy + dz * dz + dw * dw;
    __syncthreads();
#pragma unroll
    for (int off = 128; off; off >>= 1) {
        if (tid < off) red[tid] += red[tid + off];
        __syncthreads();
    }
    const float var = red[0] * (1.0f / 1024.0f);
    const float rs = rsqrtf(var + 1e-5f);
    const float4 g4 = ((const float4*)gam)[tid];
    const float4 b4 = ((const float4*)bet)[tid];
    float4 o;
    o.x = g4.x * dx * rs + b4.x;
    o.y = g4.y * dy * rs + b4.y;
    o.z = g4.z * dz * rs + b4.z;
    o.w = g4.w * dw * rs + b4.w;
    ((float4*)out)[(long)row * 256 + tid] = o;
}

// ---------------- launch ----------------
extern "C" void kernel_launch(void* const* d_in, const int* in_sizes, int n_in,
                              void* d_out, int out_size) {
    const float* Qin  = (const float*)d_in[0];
    const float* Kin  = (const float*)d_in[1];
    const float* Vin  = (const float*)d_in[2];
    const unsigned char* mask = (const unsigned char*)d_in[3];
    const float* W_q  = (const float*)d_in[4];
    const float* W_k  = (const float*)d_in[5];
    const float* W_v  = (const float*)d_in[6];
    const float* W_o  = (const float*)d_in[7];
    const float* w1   = (const float*)d_in[8];
    const float* b1   = (const float*)d_in[9];
    const float* w2   = (const float*)d_in[10];
    const float* b2   = (const float*)d_in[11];
    const float* ln_g = (const float*)d_in[12];
    const float* ln_b = (const float*)d_in[13];

    float *q_, *k_, *v_, *vatt_, *y_, *x_, *h_, *attfb_;
    cudaGetSymbolAddress((void**)&q_,    g_q);
    cudaGetSymbolAddress((void**)&k_,    g_k);
    cudaGetSymbolAddress((void**)&v_,    g_v);
    cudaGetSymbolAddress((void**)&vatt_, g_vatt);
    cudaGetSymbolAddress((void**)&y_,    g_y);
    cudaGetSymbolAddress((void**)&x_,    g_x);
    cudaGetSymbolAddress((void**)&h_,    g_h);
    cudaGetSymbolAddress((void**)&attfb_, g_att_fb);

    __nv_bfloat16 *ahi, *alo, *wqh, *wql, *wkh, *wkl, *wvh, *wvl, *woh, *wol, *w1h, *w1l, *w2h, *w2l;
    cudaGetSymbolAddress((void**)&ahi, g_ahi);
    cudaGetSymbolAddress((void**)&alo, g_alo);
    cudaGetSymbolAddress((void**)&wqh, g_wqh); cudaGetSymbolAddress((void**)&wql, g_wql);
    cudaGetSymbolAddress((void**)&wkh, g_wkh); cudaGetSymbolAddress((void**)&wkl, g_wkl);
    cudaGetSymbolAddress((void**)&wvh, g_wvh); cudaGetSymbolAddress((void**)&wvl, g_wvl);
    cudaGetSymbolAddress((void**)&woh, g_woh); cudaGetSymbolAddress((void**)&wol, g_wol);
    cudaGetSymbolAddress((void**)&w1h, g_w1h); cudaGetSymbolAddress((void**)&w1l, g_w1l);
    cudaGetSymbolAddress((void**)&w2h, g_w2h); cudaGetSymbolAddress((void**)&w2l, g_w2l);

    float* out = (float*)d_out;
    float* att = (out_size >= (int)(OUT_MAIN + OUT_ATT)) ? (out + OUT_MAIN) : attfb_;

    cudaFuncSetAttribute(mma_gemm<0>, cudaFuncAttributeMaxDynamicSharedMemorySize, GEMM_SMEM);
    cudaFuncSetAttribute(mma_gemm<1>, cudaFuncAttributeMaxDynamicSharedMemorySize, GEMM_SMEM);
    cudaFuncSetAttribute(mma_gemm<2>, cudaFuncAttributeMaxDynamicSharedMemorySize, GEMM_SMEM);
    cudaFuncSetAttribute(mma_gemm<3>, cudaFuncAttributeMaxDynamicSharedMemorySize, GEMM_SMEM);

    const dim3 tg(32, 32), tb(32, 8);
    split_transpose<<<tg, tb>>>(W_q, wqh, wql);
    split_transpose<<<tg, tb>>>(W_k, wkh, wkl);
    split_transpose<<<tg, tb>>>(W_v, wvh, wvl);
    split_transpose<<<tg, tb>>>(W_o, woh, wol);
    split_kernel<<<DM * DM / 1024, 256>>>(w1, w1h, w1l);
    split_kernel<<<DM * DM / 1024, 256>>>(w2, w2h, w2l);

    const dim3 gG(8, 64), bG(256);
    const int actBlocks = MROWS * DM / 1024;

    split_kernel<<<actBlocks, 256>>>(Qin, ahi, alo);
    mma_gemm<0><<<gG, bG, GEMM_SMEM>>>(ahi, alo, wqh, wql, q_, nullptr, nullptr);
    split_kernel<<<actBlocks, 256>>>(Kin, ahi, alo);
    mma_gemm<0><<<gG, bG, GEMM_SMEM>>>(ahi, alo, wkh, wkl, k_, nullptr, nullptr);
    split_kernel<<<actBlocks, 256>>>(Vin, ahi, alo);
    mma_gemm<0><<<gG, bG, GEMM_SMEM>>>(ahi, alo, wvh, wvl, v_, nullptr, nullptr);

    cudaFuncSetAttribute(attn_kernel, cudaFuncAttributeMaxDynamicSharedMemorySize, SMEM_ATTN);
    attn_kernel<<<dim3(SEQ / QT, BB * NH), 256, SMEM_ATTN>>>(q_, k_, v_, mask, att, vatt_);

    split_kernel<<<actBlocks, 256>>>(vatt_, ahi, alo);
    mma_gemm<1><<<gG, bG, GEMM_SMEM>>>(ahi, alo, woh, wol, y_, Qin, nullptr);
    ln_kernel<<<MROWS, 256>>>(y_, ln_g, ln_b, x_);
    split_kernel<<<actBlocks, 256>>>(x_, ahi, alo);
    mma_gemm<2><<<gG, bG, GEMM_SMEM>>>(ahi, alo, w1h, w1l, h_, nullptr, b1);
    split_kernel<<<actBlocks, 256>>>(h_, ahi, alo);
    mma_gemm<3><<<gG, bG, GEMM_SMEM>>>(ahi, alo, w2h, w2l, y_, x_, b2);
    ln_kernel<<<MROWS, 256>>>(y_, ln_g, ln_b, out);
}

// round 6
// speedup vs baseline: 2.4448x; 1.7739x over previous
#include <cuda_runtime.h>
#include <cuda_bf16.h>
#include <math.h>
#include <stdint.h>

// ---------------- problem dims ----------------
#define BB   8
#define SEQ  1024
#define DM   1024
#define NH   16
#define DK   64
#define MROWS (BB*SEQ)          // 8192
#define OUT_MAIN  (BB*SEQ*DM)              // 8388608
#define OUT_ATT   (BB*NH*SEQ*SEQ)          // 134217728

// ---------------- scratch ----------------
__device__ float g_vatt[OUT_MAIN];
__device__ float g_y[OUT_MAIN];
__device__ float g_x[OUT_MAIN];
__device__ float g_h[OUT_MAIN];
__device__ float g_att_fb[OUT_ATT];

__device__ __align__(128) __nv_bfloat16 g_ahi[MROWS*DM];
__device__ __align__(128) __nv_bfloat16 g_alo[MROWS*DM];
__device__ __align__(128) __nv_bfloat16 g_qh[MROWS*DM], g_ql[MROWS*DM];
__device__ __align__(128) __nv_bfloat16 g_kh[MROWS*DM], g_kl[MROWS*DM];
__device__ __align__(128) __nv_bfloat16 g_vh[MROWS*DM], g_vl[MROWS*DM];
__device__ __align__(128) __nv_bfloat16 g_wqh[DM*DM], g_wql[DM*DM];
__device__ __align__(128) __nv_bfloat16 g_wkh[DM*DM], g_wkl[DM*DM];
__device__ __align__(128) __nv_bfloat16 g_wvh[DM*DM], g_wvl[DM*DM];
__device__ __align__(128) __nv_bfloat16 g_woh[DM*DM], g_wol[DM*DM];
__device__ __align__(128) __nv_bfloat16 g_w1h[DM*DM], g_w1l[DM*DM];
__device__ __align__(128) __nv_bfloat16 g_w2h[DM*DM], g_w2l[DM*DM];

// ---------------- helpers ----------------
__device__ __forceinline__ uint32_t cvta_s(const void* p) {
    return (uint32_t)__cvta_generic_to_shared(p);
}
__device__ __forceinline__ void ldsm4(uint32_t r[4], uint32_t a) {
    asm volatile("ldmatrix.sync.aligned.m8n8.x4.shared.b16 {%0,%1,%2,%3}, [%4];"
                 : "=r"(r[0]), "=r"(r[1]), "=r"(r[2]), "=r"(r[3]) : "r"(a));
}
__device__ __forceinline__ void ldsm2(uint32_t r[2], uint32_t a) {
    asm volatile("ldmatrix.sync.aligned.m8n8.x2.shared.b16 {%0,%1}, [%2];"
                 : "=r"(r[0]), "=r"(r[1]) : "r"(a));
}
__device__ __forceinline__ void ldsm2t(uint32_t r[2], uint32_t a) {
    asm volatile("ldmatrix.sync.aligned.m8n8.x2.trans.shared.b16 {%0,%1}, [%2];"
                 : "=r"(r[0]), "=r"(r[1]) : "r"(a));
}
__device__ __forceinline__ void mma_bf16(float c[4], const uint32_t a[4], const uint32_t b[2]) {
    asm volatile(
        "mma.sync.aligned.m16n8k16.row.col.f32.bf16.bf16.f32 "
        "{%0,%1,%2,%3}, {%4,%5,%6,%7}, {%8,%9}, {%0,%1,%2,%3};"
        : "+f"(c[0]), "+f"(c[1]), "+f"(c[2]), "+f"(c[3])
        : "r"(a[0]), "r"(a[1]), "r"(a[2]), "r"(a[3]), "r"(b[0]), "r"(b[1]));
}
__device__ __forceinline__ void cp16(uint32_t d, const void* g) {
    asm volatile("cp.async.cg.shared.global [%0], [%1], 16;" :: "r"(d), "l"(g));
}
#define CP_COMMIT() asm volatile("cp.async.commit_group;" ::: "memory")

// ---------------- fast exp (FMA-only) ----------------
__device__ __forceinline__ float fast_exp(float x) {
    if (x < -87.0f) return 0.0f;
    float t  = x * 1.4426950408889634f;
    float fi = floorf(t);
    float f  = t - fi;
    float p  = 1.5403530e-4f;
    p = fmaf(p, f, 1.3333558e-3f);
    p = fmaf(p, f, 9.6181291e-3f);
    p = fmaf(p, f, 5.5504109e-2f);
    p = fmaf(p, f, 2.4022651e-1f);
    p = fmaf(p, f, 6.9314718e-1f);
    p = fmaf(p, f, 1.0f);
    return __int_as_float(((int)fi + 127) << 23) * p;
}

// ---------------- bf16 split kernels ----------------
__global__ void __launch_bounds__(256) split_kernel(
    const float* __restrict__ in, __nv_bfloat16* __restrict__ hi,
    __nv_bfloat16* __restrict__ lo)
{
    const int i = blockIdx.x * 256 + threadIdx.x;
    const float4 v = ((const float4*)in)[i];
    __nv_bfloat16 h0 = __float2bfloat16(v.x);
    __nv_bfloat16 h1 = __float2bfloat16(v.y);
    __nv_bfloat16 h2 = __float2bfloat16(v.z);
    __nv_bfloat16 h3 = __float2bfloat16(v.w);
    __nv_bfloat16 l0 = __float2bfloat16(v.x - __bfloat162float(h0));
    __nv_bfloat16 l1 = __float2bfloat16(v.y - __bfloat162float(h1));
    __nv_bfloat16 l2 = __float2bfloat16(v.z - __bfloat162float(h2));
    __nv_bfloat16 l3 = __float2bfloat16(v.w - __bfloat162float(h3));
    __nv_bfloat162 hp0; hp0.x = h0; hp0.y = h1;
    __nv_bfloat162 hp1; hp1.x = h2; hp1.y = h3;
    __nv_bfloat162 lp0; lp0.x = l0; lp0.y = l1;
    __nv_bfloat162 lp1; lp1.x = l2; lp1.y = l3;
    ((__nv_bfloat162*)hi)[i*2]   = hp0;
    ((__nv_bfloat162*)hi)[i*2+1] = hp1;
    ((__nv_bfloat162*)lo)[i*2]   = lp0;
    ((__nv_bfloat162*)lo)[i*2+1] = lp1;
}

// weights [K][N] -> split transposed [N][K]
__global__ void __launch_bounds__(256) split_transpose(
    const float* __restrict__ in, __nv_bfloat16* __restrict__ hi,
    __nv_bfloat16* __restrict__ lo)
{
    __shared__ float t[32][33];
    const int bx = blockIdx.x * 32, by = blockIdx.y * 32;
    const int txx = threadIdx.x, tyy = threadIdx.y;
#pragma unroll
    for (int j = 0; j < 32; j += 8)
        t[tyy + j][txx] = in[(by + tyy + j) * 1024 + bx + txx];
    __syncthreads();
#pragma unroll
    for (int j = 0; j < 32; j += 8) {
        const float v = t[txx][tyy + j];
        __nv_bfloat16 h = __float2bfloat16(v);
        __nv_bfloat16 l = __float2bfloat16(v - __bfloat162float(h));
        const int idx = (bx + tyy + j) * 1024 + by + txx;
        hi[idx] = h;
        lo[idx] = l;
    }
}

// ---------------- HMMA bf16x3 GEMM ----------------
// MODE 0: scatter to [B,H,S,64] as bf16 hi/lo pair   MODE 1: +res   MODE 2: gelu(+bias)   MODE 3: +bias+res
#define ROWB 80
#define ASTG 10240
#define STG  40960
#define GEMM_SMEM (2 * STG)

template<int MODE>
__global__ void __launch_bounds__(256) mma_gemm(
    const __nv_bfloat16* __restrict__ Ahi, const __nv_bfloat16* __restrict__ Alo,
    const __nv_bfloat16* __restrict__ Bhi, const __nv_bfloat16* __restrict__ Blo,
    float* __restrict__ C, const float* __restrict__ res, const float* __restrict__ bias,
    __nv_bfloat16* __restrict__ Chi, __nv_bfloat16* __restrict__ Clo)
{
    extern __shared__ __align__(128) char smem[];
    const int tid = threadIdx.x;
    const int lane = tid & 31, w = tid >> 5;
    const int wm = w >> 2, wn = w & 3;
    const int m0 = blockIdx.y * 128, n0 = blockIdx.x * 128;
    const uint32_t sbase = cvta_s(smem);

    float acc[4][4][4];
#pragma unroll
    for (int i = 0; i < 4; i++)
#pragma unroll
        for (int j = 0; j < 4; j++)
#pragma unroll
            for (int k = 0; k < 4; k++) acc[i][j][k] = 0.0f;

    const __nv_bfloat16* gsrc[4] = {Ahi, Alo, Bhi, Blo};

    auto fill = [&](int buf, int kc) {
        const int k0 = kc * 32;
        const uint32_t dst0 = sbase + buf * STG;
#pragma unroll
        for (int i = 0; i < 8; i++) {
            const int idx = i * 256 + tid;
            const int arr = idx >> 9;
            const int within = idx & 511;
            const int row = within >> 2, seg = within & 3;
            const int grow = (arr < 2 ? m0 : n0) + row;
            const __nv_bfloat16* g = gsrc[arr] + (long)grow * 1024 + k0 + seg * 8;
            cp16(dst0 + arr * ASTG + row * ROWB + seg * 16, g);
        }
        CP_COMMIT();
    };

    fill(0, 0);
    for (int c = 0; c < 32; c++) {
        const int buf = c & 1;
        if (c + 1 < 32) {
            fill(buf ^ 1, c + 1);
            asm volatile("cp.async.wait_group 1;" ::: "memory");
        } else {
            asm volatile("cp.async.wait_group 0;" ::: "memory");
        }
        __syncthreads();

        const uint32_t sb = sbase + buf * STG;
#pragma unroll
        for (int s = 0; s < 2; s++) {
            uint32_t ah[4][4], al[4][4], bh[4][2], bl[4][2];
            const int acol = (s * 16 + (lane >> 4) * 8) * 2;
            const int arow = lane & 15;
#pragma unroll
            for (int mt = 0; mt < 4; mt++) {
                const uint32_t ao = sb + (wm * 64 + mt * 16 + arow) * ROWB + acol;
                ldsm4(ah[mt], ao);
                ldsm4(al[mt], ao + ASTG);
            }
            const int le = lane & 15;
            const int bcol = (s * 16 + ((le >> 3) & 1) * 8) * 2;
            const int brow = le & 7;
#pragma unroll
            for (int nt = 0; nt < 4; nt++) {
                const uint32_t bo = sb + 2 * ASTG + (wn * 32 + nt * 8 + brow) * ROWB + bcol;
                ldsm2(bh[nt], bo);
                ldsm2(bl[nt], bo + ASTG);
            }
#pragma unroll
            for (int mt = 0; mt < 4; mt++)
#pragma unroll
                for (int nt = 0; nt < 4; nt++) {
                    mma_bf16(acc[mt][nt], ah[mt], bh[nt]);
                    mma_bf16(acc[mt][nt], ah[mt], bl[nt]);
                    mma_bf16(acc[mt][nt], al[mt], bh[nt]);
                }
        }
        __syncthreads();
    }

    // ---- epilogue ----
    const int g = lane >> 2, t4 = lane & 3;
#pragma unroll
    for (int mt = 0; mt < 4; mt++) {
#pragma unroll
        for (int half = 0; half < 2; half++) {
            const int m = m0 + wm * 64 + mt * 16 + g + half * 8;
#pragma unroll
            for (int nt = 0; nt < 4; nt++) {
                const int n = n0 + wn * 32 + nt * 8 + t4 * 2;
                float v0 = acc[mt][nt][half * 2 + 0];
                float v1 = acc[mt][nt][half * 2 + 1];
                if (MODE == 0) {
                    const int b = m >> 10, s = m & 1023, h = n >> 6, d = n & 63;
                    const long off = ((long)((b * 16 + h) * 1024 + s)) * 64 + d;
                    __nv_bfloat162 h2, l2;
                    h2.x = __float2bfloat16(v0);
                    h2.y = __float2bfloat16(v1);
                    l2.x = __float2bfloat16(v0 - __bfloat162float(h2.x));
                    l2.y = __float2bfloat16(v1 - __bfloat162float(h2.y));
                    *(__nv_bfloat162*)(Chi + off) = h2;
                    *(__nv_bfloat162*)(Clo + off) = l2;
                } else if (MODE == 1) {
                    const float2 r2 = *(const float2*)&res[(long)m * 1024 + n];
                    float2 o; o.x = v0 + r2.x; o.y = v1 + r2.y;
                    *(float2*)&C[(long)m * 1024 + n] = o;
                } else if (MODE == 2) {
                    const float2 bi = *(const float2*)&bias[n];
                    const float is2 = 0.70710678118654752f;
                    float x0 = v0 + bi.x, x1 = v1 + bi.y;
                    float2 o;
                    o.x = 0.5f * x0 * (1.0f + erff(x0 * is2));
                    o.y = 0.5f * x1 * (1.0f + erff(x1 * is2));
                    *(float2*)&C[(long)m * 1024 + n] = o;
                } else {
                    const float2 bi = *(const float2*)&bias[n];
                    const float2 r2 = *(const float2*)&res[(long)m * 1024 + n];
                    float2 o; o.x = v0 + bi.x + r2.x; o.y = v1 + bi.y + r2.y;
                    *(float2*)&C[(long)m * 1024 + n] = o;
                }
            }
        }
    }
}

// ---------------- HMMA attention ----------------
// Block = (16 q rows, one bh). 256 threads (8 warps).
// smem layout (bytes):
//  Qh 0..2304, Ql 2304..4608
//  KV: 4608 + buf*18432 + {0:hi,9216:lo}   (2 buffers)
//  Ss fp32 [16][1032]   at 41472  (66048)
//  Ph bf16 [16][1032]   at 107520 (33024)
//  Pl bf16 [16][1032]   at 140544 (33024)
#define SM_QH 0
#define SM_QL 2304
#define SM_KV 4608
#define SM_SS 41472
#define SM_PH 107520
#define SM_PL 140544
#define ATTN_SMEM 173568
#define SSP 1032

__global__ void __launch_bounds__(256) attn2(
    const __nv_bfloat16* __restrict__ qh, const __nv_bfloat16* __restrict__ ql,
    const __nv_bfloat16* __restrict__ kh, const __nv_bfloat16* __restrict__ kl,
    const __nv_bfloat16* __restrict__ vh, const __nv_bfloat16* __restrict__ vl,
    const unsigned char* __restrict__ mask,
    float* __restrict__ att, float* __restrict__ vatt)
{
    extern __shared__ __align__(128) char sm[];
    __shared__ int s_any;
    const uint32_t sbase = cvta_s(sm);
    const int tid = threadIdx.x;
    const int lane = tid & 31, w = tid >> 5;
    const int qt = blockIdx.x, bh = blockIdx.y;
    const int b = bh >> 4, h = bh & 15;
    const int q0 = qt * 16;
    const long base = (long)bh * SEQ * 64;
    const float scale = 1.0f / (8.0f + 1e-6f);
    float* Ss = (float*)(sm + SM_SS);

    auto fillKV = [&](const __nv_bfloat16* phi_, const __nv_bfloat16* plo_, int buf, int kt) {
#pragma unroll
        for (int i = 0; i < 4; i++) {
            const int idx = i * 256 + tid;
            const int arr = idx >> 9;
            const int wi = idx & 511;
            const int row = wi >> 3, seg = wi & 7;
            const __nv_bfloat16* g = (arr ? plo_ : phi_) + base + (long)(kt * 64 + row) * 64 + seg * 8;
            cp16(sbase + SM_KV + buf * 18432 + arr * 9216 + row * 144 + seg * 16, g);
        }
        CP_COMMIT();
    };

    // ---- load Q (hi/lo) + K chunk 0 ----
    {
        const int arr = tid >> 7;
        const int wi = tid & 127;
        const int row = wi >> 3, seg = wi & 7;
        const __nv_bfloat16* g = (arr ? ql : qh) + base + (long)(q0 + row) * 64 + seg * 8;
        cp16(sbase + (arr ? SM_QL : SM_QH) + row * 144 + seg * 16, g);
    }
    if (tid == 0) s_any = 0;
    fillKV(kh, kl, 0, 0);   // group0 = Q + K0

    if (tid < 16 && mask[b * SEQ + q0 + tid]) s_any = 1;

    const int kt_max = (q0 + 15) >> 6;

    // ---- phase 1: scores ----
    uint32_t ah[4][4], al[4][4];
    for (int kt = 0; kt <= kt_max; kt++) {
        const int buf = kt & 1;
        if (kt < kt_max) {
            fillKV(kh, kl, buf ^ 1, kt + 1);
            asm volatile("cp.async.wait_group 1;" ::: "memory");
        } else {
            asm volatile("cp.async.wait_group 0;" ::: "memory");
        }
        __syncthreads();
        if (kt == 0) {
#pragma unroll
            for (int s = 0; s < 4; s++) {
                const uint32_t qa = sbase + (lane & 15) * 144 + s * 32 + (lane >> 4) * 16;
                ldsm4(ah[s], qa + SM_QH);
                ldsm4(al[s], qa + SM_QL);
            }
        }
        const uint32_t khb = sbase + SM_KV + buf * 18432;
        const int le = lane & 15;
        float c[4] = {0, 0, 0, 0};
#pragma unroll
        for (int s = 0; s < 4; s++) {
            uint32_t bhr[2], blr[2];
            const uint32_t ka = khb + (w * 8 + (le & 7)) * 144 + s * 32 + ((le >> 3) & 1) * 16;
            ldsm2(bhr, ka);
            ldsm2(blr, ka + 9216);
            mma_bf16(c, ah[s], bhr);
            mma_bf16(c, ah[s], blr);
            mma_bf16(c, al[s], bhr);
        }
        const int r = lane >> 2, col = kt * 64 + w * 8 + (lane & 3) * 2;
        float2 st0; st0.x = c[0] * scale; st0.y = c[1] * scale;
        float2 st1; st1.x = c[2] * scale; st1.y = c[3] * scale;
        *(float2*)(Ss + r * SSP + col) = st0;
        *(float2*)(Ss + (r + 8) * SSP + col) = st1;
        __syncthreads();
    }

    const int kt_end = s_any ? (SEQ / 64 - 1) : kt_max;

    // prefetch V chunk 0 (buffers free; overlaps softmax)
    fillKV(vh, vl, 0, 0);

    // ---- phase 2: softmax (16 threads/row) ----
    {
        const int r = tid >> 4, tc = tid & 15;
        const int qg = q0 + r;
        const int limit = qg;
        const bool rmask = mask[b * SEQ + qg] != 0;
        float* srow = Ss + r * SSP;

        float mx = -3.4e38f;
#pragma unroll 4
        for (int j = 0; j < 64; j++) {
            const int k = tc + (j << 4);
            if (k <= limit) mx = fmaxf(mx, srow[k]);
        }
#pragma unroll
        for (int off = 8; off; off >>= 1)
            mx = fmaxf(mx, __shfl_xor_sync(0xffffffffu, mx, off, 16));

        float l = 0.0f;
#pragma unroll 4
        for (int j = 0; j < 64; j++) {
            const int k = tc + (j << 4);
            if (k <= limit) {
                const float e = fast_exp(srow[k] - mx);
                srow[k] = e;
                l += e;
            }
        }
#pragma unroll
        for (int off = 8; off; off >>= 1)
            l += __shfl_xor_sync(0xffffffffu, l, off, 16);
        const float inv = 1.0f / l;
        const float invS = 1.0f / (float)SEQ;

        float* attrow = att + ((long)bh * SEQ + qg) * SEQ;
        __nv_bfloat16* phrow = (__nv_bfloat16*)(sm + SM_PH) + r * SSP;
        __nv_bfloat16* plrow = (__nv_bfloat16*)(sm + SM_PL) + r * SSP;
#pragma unroll 4
        for (int j = 0; j < 64; j++) {
            const int k = tc + (j << 4);
            float p;
            if (rmask)           p = invS;
            else if (k <= limit) p = srow[k] * inv;
            else                 p = 0.0f;
            attrow[k] = p;
            const __nv_bfloat16 hi = __float2bfloat16(p);
            phrow[k] = hi;
            plrow[k] = __float2bfloat16(p - __bfloat162float(hi));
        }
    }
    __syncthreads();

    // ---- phase 3: AV ----
    float o[4] = {0, 0, 0, 0};
    for (int kt = 0; kt <= kt_end; kt++) {
        const int buf = kt & 1;
        if (kt < kt_end) {
            fillKV(vh, vl, buf ^ 1, kt + 1);
            asm volatile("cp.async.wait_group 1;" ::: "memory");
        } else {
            asm volatile("cp.async.wait_group 0;" ::: "memory");
        }
        __syncthreads();
        const uint32_t vbh = sbase + SM_KV + buf * 18432;
#pragma unroll
        for (int s = 0; s < 4; s++) {
            uint32_t pa[4], pb[4], vvh[2], vvl[2];
            const uint32_t colb = (kt * 64 + s * 16) * 2 + (lane >> 4) * 16;
            const uint32_t prow = (lane & 15) * 2064;
            ldsm4(pa, sbase + SM_PH + prow + colb);
            ldsm4(pb, sbase + SM_PL + prow + colb);
            const uint32_t va = vbh + (s * 16 + (lane & 15)) * 144 + w * 16;
            ldsm2t(vvh, va);
            ldsm2t(vvl, va + 9216);
            mma_bf16(o, pa, vvh);
            mma_bf16(o, pa, vvl);
            mma_bf16(o, pb, vvh);
        }
        __syncthreads();
    }

    // epilogue: warp w -> dv cols w*8..+7
    const int r = lane >> 2, dv = w * 8 + (lane & 3) * 2;
    float* dst0 = vatt + ((long)(b * SEQ + q0 + r)) * 1024 + h * 64 + dv;
    float* dst1 = vatt + ((long)(b * SEQ + q0 + r + 8)) * 1024 + h * 64 + dv;
    float2 o0; o0.x = o[0]; o0.y = o[1];
    float2 o1; o1.x = o[2]; o1.y = o[3];
    *(float2*)dst0 = o0;
    *(float2*)dst1 = o1;
}

// ---------------- layernorm ----------------
__global__ void __launch_bounds__(256) ln_kernel(
    const float* __restrict__ x, const float* __restrict__ gam,
    const float* __restrict__ bet, float* __restrict__ out)
{
    __shared__ float red[256];
    const int row = blockIdx.x, tid = threadIdx.x;
    const float4 v = ((const float4*)x)[(long)row * 256 + tid];
    red[tid] = v.x + v.y + v.z + v.w;
    __syncthreads();
#pragma unroll
    for (int off = 128; off; off >>= 1) {
        if (tid < off) red[tid] += red[tid + off];
        __syncthreads();
    }
    const float mu = red[0] * (1.0f / 1024.0f);
    __syncthreads();
    const float dx = v.x - mu, dy = v.y - mu, dz = v.z - mu, dw = v.w - mu;
    red[tid] = dx * dx + dy * dy + dz * dz + dw * dw;
    __syncthreads();
#pragma unroll
    for (int off = 128; off; off >>= 1) {
        if (tid < off) red[tid] += red[tid + off];
        __syncthreads();
    }
    const float var = red[0] * (1.0f / 1024.0f);
    const float rs = rsqrtf(var + 1e-5f);
    const float4 g4 = ((const float4*)gam)[tid];
    const float4 b4 = ((const float4*)bet)[tid];
    float4 o;
    o.x = g4.x * dx * rs + b4.x;
    o.y = g4.y * dy * rs + b4.y;
    o.z = g4.z * dz * rs + b4.z;
    o.w = g4.w * dw * rs + b4.w;
    ((float4*)out)[(long)row * 256 + tid] = o;
}

// ---------------- launch ----------------
extern "C" void kernel_launch(void* const* d_in, const int* in_sizes, int n_in,
                              void* d_out, int out_size) {
    const float* Qin  = (const float*)d_in[0];
    const float* Kin  = (const float*)d_in[1];
    const float* Vin  = (const float*)d_in[2];
    const unsigned char* mask = (const unsigned char*)d_in[3];
    const float* W_q  = (const float*)d_in[4];
    const float* W_k  = (const float*)d_in[5];
    const float* W_v  = (const float*)d_in[6];
    const float* W_o  = (const float*)d_in[7];
    const float* w1   = (const float*)d_in[8];
    const float* b1   = (const float*)d_in[9];
    const float* w2   = (const float*)d_in[10];
    const float* b2   = (const float*)d_in[11];
    const float* ln_g = (const float*)d_in[12];
    const float* ln_b = (const float*)d_in[13];

    float *vatt_, *y_, *x_, *h_, *attfb_;
    cudaGetSymbolAddress((void**)&vatt_, g_vatt);
    cudaGetSymbolAddress((void**)&y_,    g_y);
    cudaGetSymbolAddress((void**)&x_,    g_x);
    cudaGetSymbolAddress((void**)&h_,    g_h);
    cudaGetSymbolAddress((void**)&attfb_, g_att_fb);

    __nv_bfloat16 *ahi, *alo, *qh_, *ql_, *kh_, *kl_, *vh_, *vl_;
    __nv_bfloat16 *wqh, *wql, *wkh, *wkl, *wvh, *wvl, *woh, *wol, *w1h, *w1l, *w2h, *w2l;
    cudaGetSymbolAddress((void**)&ahi, g_ahi);
    cudaGetSymbolAddress((void**)&alo, g_alo);
    cudaGetSymbolAddress((void**)&qh_, g_qh); cudaGetSymbolAddress((void**)&ql_, g_ql);
    cudaGetSymbolAddress((void**)&kh_, g_kh); cudaGetSymbolAddress((void**)&kl_, g_kl);
    cudaGetSymbolAddress((void**)&vh_, g_vh); cudaGetSymbolAddress((void**)&vl_, g_vl);
    cudaGetSymbolAddress((void**)&wqh, g_wqh); cudaGetSymbolAddress((void**)&wql, g_wql);
    cudaGetSymbolAddress((void**)&wkh, g_wkh); cudaGetSymbolAddress((void**)&wkl, g_wkl);
    cudaGetSymbolAddress((void**)&wvh, g_wvh); cudaGetSymbolAddress((void**)&wvl, g_wvl);
    cudaGetSymbolAddress((void**)&woh, g_woh); cudaGetSymbolAddress((void**)&wol, g_wol);
    cudaGetSymbolAddress((void**)&w1h, g_w1h); cudaGetSymbolAddress((void**)&w1l, g_w1l);
    cudaGetSymbolAddress((void**)&w2h, g_w2h); cudaGetSymbolAddress((void**)&w2l, g_w2l);

    float* out = (float*)d_out;
    float* att = (out_size >= (int)(OUT_MAIN + OUT_ATT)) ? (out + OUT_MAIN) : attfb_;

    cudaFuncSetAttribute(mma_gemm<0>, cudaFuncAttributeMaxDynamicSharedMemorySize, GEMM_SMEM);
    cudaFuncSetAttribute(mma_gemm<1>, cudaFuncAttributeMaxDynamicSharedMemorySize, GEMM_SMEM);
    cudaFuncSetAttribute(mma_gemm<2>, cudaFuncAttributeMaxDynamicSharedMemorySize, GEMM_SMEM);
    cudaFuncSetAttribute(mma_gemm<3>, cudaFuncAttributeMaxDynamicSharedMemorySize, GEMM_SMEM);
    cudaFuncSetAttribute(attn2, cudaFuncAttributeMaxDynamicSharedMemorySize, ATTN_SMEM);

    const dim3 tg(32, 32), tb(32, 8);
    split_transpose<<<tg, tb>>>(W_q, wqh, wql);
    split_transpose<<<tg, tb>>>(W_k, wkh, wkl);
    split_transpose<<<tg, tb>>>(W_v, wvh, wvl);
    split_transpose<<<tg, tb>>>(W_o, woh, wol);
    split_kernel<<<DM * DM / 1024, 256>>>(w1, w1h, w1l);
    split_kernel<<<DM * DM / 1024, 256>>>(w2, w2h, w2l);

    const dim3 gG(8, 64), bG(256);
    const int actBlocks = MROWS * DM / 1024;

    split_kernel<<<actBlocks, 256>>>(Qin, ahi, alo);
    mma_gemm<0><<<gG, bG, GEMM_SMEM>>>(ahi, alo, wqh, wql, nullptr, nullptr, nullptr, qh_, ql_);
    split_kernel<<<actBlocks, 256>>>(Kin, ahi, alo);
    mma_gemm<0><<<gG, bG, GEMM_SMEM>>>(ahi, alo, wkh, wkl, nullptr, nullptr, nullptr, kh_, kl_);
    split_kernel<<<actBlocks, 256>>>(Vin, ahi, alo);
    mma_gemm<0><<<gG, bG, GEMM_SMEM>>>(ahi, alo, wvh, wvl, nullptr, nullptr, nullptr, vh_, vl_);

    attn2<<<dim3(SEQ / 16, BB * NH), 256, ATTN_SMEM>>>(qh_, ql_, kh_, kl_, vh_, vl_, mask, att, vatt_);

    split_kernel<<<actBlocks, 256>>>(vatt_, ahi, alo);
    mma_gemm<1><<<gG, bG, GEMM_SMEM>>>(ahi, alo, woh, wol, y_, Qin, nullptr, nullptr, nullptr);
    ln_kernel<<<MROWS, 256>>>(y_, ln_g, ln_b, x_);
    split_kernel<<<actBlocks, 256>>>(x_, ahi, alo);
    mma_gemm<2><<<gG, bG, GEMM_SMEM>>>(ahi, alo, w1h, w1l, h_, nullptr, b1, nullptr, nullptr);
    split_kernel<<<actBlocks, 256>>>(h_, ahi, alo);
    mma_gemm<3><<<gG, bG, GEMM_SMEM>>>(ahi, alo, w2h, w2l, y_, x_, b2, nullptr, nullptr);
    ln_kernel<<<MROWS, 256>>>(y_, ln_g, ln_b, out);
}

// round 7
// speedup vs baseline: 2.4864x; 1.0170x over previous
#include <cuda_runtime.h>
#include <cuda_bf16.h>
#include <math.h>
#include <stdint.h>

// ---------------- problem dims ----------------
#define BB   8
#define SEQ  1024
#define DM   1024
#define NH   16
#define DK   64
#define MROWS (BB*SEQ)          // 8192
#define OUT_MAIN  (BB*SEQ*DM)              // 8388608
#define OUT_ATT   (BB*NH*SEQ*SEQ)          // 134217728

// ---------------- scratch ----------------
__device__ __align__(128) float g_y[OUT_MAIN];
__device__ __align__(128) float g_x[OUT_MAIN];
__device__ float g_att_fb[OUT_ATT];

__device__ __align__(128) __nv_bfloat16 g_ahi[MROWS*DM];
__device__ __align__(128) __nv_bfloat16 g_alo[MROWS*DM];
__device__ __align__(128) __nv_bfloat16 g_qh[MROWS*DM], g_ql[MROWS*DM];
__device__ __align__(128) __nv_bfloat16 g_kh[MROWS*DM], g_kl[MROWS*DM];
__device__ __align__(128) __nv_bfloat16 g_vh[MROWS*DM], g_vl[MROWS*DM];
__device__ __align__(128) __nv_bfloat16 g_wqh[DM*DM], g_wql[DM*DM];
__device__ __align__(128) __nv_bfloat16 g_wkh[DM*DM], g_wkl[DM*DM];
__device__ __align__(128) __nv_bfloat16 g_wvh[DM*DM], g_wvl[DM*DM];
__device__ __align__(128) __nv_bfloat16 g_woh[DM*DM], g_wol[DM*DM];
__device__ __align__(128) __nv_bfloat16 g_w1h[DM*DM], g_w1l[DM*DM];
__device__ __align__(128) __nv_bfloat16 g_w2h[DM*DM], g_w2l[DM*DM];

// ---------------- helpers ----------------
__device__ __forceinline__ uint32_t cvta_s(const void* p) {
    return (uint32_t)__cvta_generic_to_shared(p);
}
__device__ __forceinline__ void ldsm4(uint32_t r[4], uint32_t a) {
    asm volatile("ldmatrix.sync.aligned.m8n8.x4.shared.b16 {%0,%1,%2,%3}, [%4];"
                 : "=r"(r[0]), "=r"(r[1]), "=r"(r[2]), "=r"(r[3]) : "r"(a));
}
__device__ __forceinline__ void ldsm2(uint32_t r[2], uint32_t a) {
    asm volatile("ldmatrix.sync.aligned.m8n8.x2.shared.b16 {%0,%1}, [%2];"
                 : "=r"(r[0]), "=r"(r[1]) : "r"(a));
}
__device__ __forceinline__ void ldsm2t(uint32_t r[2], uint32_t a) {
    asm volatile("ldmatrix.sync.aligned.m8n8.x2.trans.shared.b16 {%0,%1}, [%2];"
                 : "=r"(r[0]), "=r"(r[1]) : "r"(a));
}
__device__ __forceinline__ void mma_bf16(float c[4], const uint32_t a[4], const uint32_t b[2]) {
    asm volatile(
        "mma.sync.aligned.m16n8k16.row.col.f32.bf16.bf16.f32 "
        "{%0,%1,%2,%3}, {%4,%5,%6,%7}, {%8,%9}, {%0,%1,%2,%3};"
        : "+f"(c[0]), "+f"(c[1]), "+f"(c[2]), "+f"(c[3])
        : "r"(a[0]), "r"(a[1]), "r"(a[2]), "r"(a[3]), "r"(b[0]), "r"(b[1]));
}
__device__ __forceinline__ void cp16(uint32_t d, const void* g) {
    asm volatile("cp.async.cg.shared.global [%0], [%1], 16;" :: "r"(d), "l"(g));
}
#define CP_COMMIT() asm volatile("cp.async.commit_group;" ::: "memory")

// ---------------- fast exp (FMA-only) ----------------
__device__ __forceinline__ float fast_exp(float x) {
    if (x < -87.0f) return 0.0f;
    float t  = x * 1.4426950408889634f;
    float fi = floorf(t);
    float f  = t - fi;
    float p  = 1.5403530e-4f;
    p = fmaf(p, f, 1.3333558e-3f);
    p = fmaf(p, f, 9.6181291e-3f);
    p = fmaf(p, f, 5.5504109e-2f);
    p = fmaf(p, f, 2.4022651e-1f);
    p = fmaf(p, f, 6.9314718e-1f);
    p = fmaf(p, f, 1.0f);
    return __int_as_float(((int)fi + 127) << 23) * p;
}

__device__ __forceinline__ void split2(float v0, float v1, __nv_bfloat162& h2, __nv_bfloat162& l2) {
    h2.x = __float2bfloat16(v0);
    h2.y = __float2bfloat16(v1);
    l2.x = __float2bfloat16(v0 - __bfloat162float(h2.x));
    l2.y = __float2bfloat16(v1 - __bfloat162float(h2.y));
}

// ---------------- batched split (up to 3 tensors via blockIdx.y) ----------------
__global__ void __launch_bounds__(256) splitmulti(
    const float* __restrict__ i0, const float* __restrict__ i1, const float* __restrict__ i2,
    __nv_bfloat16* __restrict__ h0, __nv_bfloat16* __restrict__ l0,
    __nv_bfloat16* __restrict__ h1, __nv_bfloat16* __restrict__ l1,
    __nv_bfloat16* __restrict__ h2p, __nv_bfloat16* __restrict__ l2p)
{
    const float* in; __nv_bfloat16 *hi, *lo;
    if      (blockIdx.y == 0) { in = i0; hi = h0;  lo = l0; }
    else if (blockIdx.y == 1) { in = i1; hi = h1;  lo = l1; }
    else                      { in = i2; hi = h2p; lo = l2p; }
    const int i = blockIdx.x * 256 + threadIdx.x;
    const float4 v = ((const float4*)in)[i];
    __nv_bfloat162 hA, lA, hB, lB;
    split2(v.x, v.y, hA, lA);
    split2(v.z, v.w, hB, lB);
    ((__nv_bfloat162*)hi)[i*2]   = hA;
    ((__nv_bfloat162*)hi)[i*2+1] = hB;
    ((__nv_bfloat162*)lo)[i*2]   = lA;
    ((__nv_bfloat162*)lo)[i*2+1] = lB;
}

// 4 weight transposes [K][N]->[N][K] via blockIdx.z
__global__ void __launch_bounds__(256) split_transpose4(
    const float* __restrict__ i0, const float* __restrict__ i1,
    const float* __restrict__ i2, const float* __restrict__ i3,
    __nv_bfloat16* __restrict__ h0, __nv_bfloat16* __restrict__ l0,
    __nv_bfloat16* __restrict__ h1, __nv_bfloat16* __restrict__ l1,
    __nv_bfloat16* __restrict__ h2, __nv_bfloat16* __restrict__ l2,
    __nv_bfloat16* __restrict__ h3, __nv_bfloat16* __restrict__ l3)
{
    const float* in; __nv_bfloat16 *hi, *lo;
    if      (blockIdx.z == 0) { in = i0; hi = h0; lo = l0; }
    else if (blockIdx.z == 1) { in = i1; hi = h1; lo = l1; }
    else if (blockIdx.z == 2) { in = i2; hi = h2; lo = l2; }
    else                      { in = i3; hi = h3; lo = l3; }
    __shared__ float t[32][33];
    const int bx = blockIdx.x * 32, by = blockIdx.y * 32;
    const int txx = threadIdx.x, tyy = threadIdx.y;
#pragma unroll
    for (int j = 0; j < 32; j += 8)
        t[tyy + j][txx] = in[(by + tyy + j) * 1024 + bx + txx];
    __syncthreads();
#pragma unroll
    for (int j = 0; j < 32; j += 8) {
        const float v = t[txx][tyy + j];
        __nv_bfloat16 h = __float2bfloat16(v);
        __nv_bfloat16 l = __float2bfloat16(v - __bfloat162float(h));
        const int idx = (bx + tyy + j) * 1024 + by + txx;
        hi[idx] = h;
        lo[idx] = l;
    }
}

// ---------------- HMMA bf16x3 GEMM ----------------
// MODE 0: scatter to [B,H,S,64] as bf16 hi/lo pair
// MODE 1: C = AB + res (fp32)
// MODE 2: gelu(AB + bias) -> bf16 hi/lo [M][1024]
// MODE 3: C = AB + bias + res (fp32)
#define ROWB 80
#define ASTG 10240
#define STG  40960
#define GEMM_SMEM (2 * STG)

template<int MODE>
__global__ void __launch_bounds__(256, 2) mma_gemm(
    const __nv_bfloat16* __restrict__ Ahi, const __nv_bfloat16* __restrict__ Alo,
    const __nv_bfloat16* __restrict__ Bhi, const __nv_bfloat16* __restrict__ Blo,
    float* __restrict__ C, const float* __restrict__ res, const float* __restrict__ bias,
    __nv_bfloat16* __restrict__ Chi, __nv_bfloat16* __restrict__ Clo)
{
    extern __shared__ __align__(128) char smem[];
    const int tid = threadIdx.x;
    const int lane = tid & 31, w = tid >> 5;
    const int wm = w >> 2, wn = w & 3;
    const int m0 = blockIdx.y * 128, n0 = blockIdx.x * 128;
    const uint32_t sbase = cvta_s(smem);

    float acc[4][4][4];
#pragma unroll
    for (int i = 0; i < 4; i++)
#pragma unroll
        for (int j = 0; j < 4; j++)
#pragma unroll
            for (int k = 0; k < 4; k++) acc[i][j][k] = 0.0f;

    const __nv_bfloat16* gsrc[4] = {Ahi, Alo, Bhi, Blo};

    auto fill = [&](int buf, int kc) {
        const int k0 = kc * 32;
        const uint32_t dst0 = sbase + buf * STG;
#pragma unroll
        for (int i = 0; i < 8; i++) {
            const int idx = i * 256 + tid;
            const int arr = idx >> 9;
            const int within = idx & 511;
            const int row = within >> 2, seg = within & 3;
            const int grow = (arr < 2 ? m0 : n0) + row;
            const __nv_bfloat16* g = gsrc[arr] + (long)grow * 1024 + k0 + seg * 8;
            cp16(dst0 + arr * ASTG + row * ROWB + seg * 16, g);
        }
        CP_COMMIT();
    };

    fill(0, 0);
    for (int c = 0; c < 32; c++) {
        const int buf = c & 1;
        if (c + 1 < 32) {
            fill(buf ^ 1, c + 1);
            asm volatile("cp.async.wait_group 1;" ::: "memory");
        } else {
            asm volatile("cp.async.wait_group 0;" ::: "memory");
        }
        __syncthreads();

        const uint32_t sb = sbase + buf * STG;
#pragma unroll
        for (int s = 0; s < 2; s++) {
            uint32_t ah[4][4], al[4][4], bh[4][2], bl[4][2];
            const int acol = (s * 16 + (lane >> 4) * 8) * 2;
            const int arow = lane & 15;
#pragma unroll
            for (int mt = 0; mt < 4; mt++) {
                const uint32_t ao = sb + (wm * 64 + mt * 16 + arow) * ROWB + acol;
                ldsm4(ah[mt], ao);
                ldsm4(al[mt], ao + ASTG);
            }
            const int le = lane & 15;
            const int bcol = (s * 16 + ((le >> 3) & 1) * 8) * 2;
            const int brow = le & 7;
#pragma unroll
            for (int nt = 0; nt < 4; nt++) {
                const uint32_t bo = sb + 2 * ASTG + (wn * 32 + nt * 8 + brow) * ROWB + bcol;
                ldsm2(bh[nt], bo);
                ldsm2(bl[nt], bo + ASTG);
            }
#pragma unroll
            for (int mt = 0; mt < 4; mt++)
#pragma unroll
                for (int nt = 0; nt < 4; nt++) {
                    mma_bf16(acc[mt][nt], ah[mt], bh[nt]);
                    mma_bf16(acc[mt][nt], ah[mt], bl[nt]);
                    mma_bf16(acc[mt][nt], al[mt], bh[nt]);
                }
        }
        __syncthreads();
    }

    // ---- epilogue ----
    const int g = lane >> 2, t4 = lane & 3;
#pragma unroll
    for (int mt = 0; mt < 4; mt++) {
#pragma unroll
        for (int half = 0; half < 2; half++) {
            const int m = m0 + wm * 64 + mt * 16 + g + half * 8;
#pragma unroll
            for (int nt = 0; nt < 4; nt++) {
                const int n = n0 + wn * 32 + nt * 8 + t4 * 2;
                float v0 = acc[mt][nt][half * 2 + 0];
                float v1 = acc[mt][nt][half * 2 + 1];
                if (MODE == 0) {
                    const int b = m >> 10, s = m & 1023, h = n >> 6, d = n & 63;
                    const long off = ((long)((b * 16 + h) * 1024 + s)) * 64 + d;
                    __nv_bfloat162 h2, l2;
                    split2(v0, v1, h2, l2);
                    *(__nv_bfloat162*)(Chi + off) = h2;
                    *(__nv_bfloat162*)(Clo + off) = l2;
                } else if (MODE == 1) {
                    const float2 r2 = *(const float2*)&res[(long)m * 1024 + n];
                    float2 o; o.x = v0 + r2.x; o.y = v1 + r2.y;
                    *(float2*)&C[(long)m * 1024 + n] = o;
                } else if (MODE == 2) {
                    const float2 bi = *(const float2*)&bias[n];
                    const float is2 = 0.70710678118654752f;
                    float x0 = v0 + bi.x, x1 = v1 + bi.y;
                    float g0 = 0.5f * x0 * (1.0f + erff(x0 * is2));
                    float g1 = 0.5f * x1 * (1.0f + erff(x1 * is2));
                    const long off = (long)m * 1024 + n;
                    __nv_bfloat162 h2, l2;
                    split2(g0, g1, h2, l2);
                    *(__nv_bfloat162*)(Chi + off) = h2;
                    *(__nv_bfloat162*)(Clo + off) = l2;
                } else {
                    const float2 bi = *(const float2*)&bias[n];
                    const float2 r2 = *(const float2*)&res[(long)m * 1024 + n];
                    float2 o; o.x = v0 + bi.x + r2.x; o.y = v1 + bi.y + r2.y;
                    *(float2*)&C[(long)m * 1024 + n] = o;
                }
            }
        }
    }
}

// ---------------- HMMA attention ----------------
#define SM_QH 0
#define SM_QL 2304
#define SM_KV 4608
#define SM_SS 41472
#define SM_PH 107520
#define SM_PL 140544
#define ATTN_SMEM 173568
#define SSP 1032

__global__ void __launch_bounds__(256) attn2(
    const __nv_bfloat16* __restrict__ qh, const __nv_bfloat16* __restrict__ ql,
    const __nv_bfloat16* __restrict__ kh, const __nv_bfloat16* __restrict__ kl,
    const __nv_bfloat16* __restrict__ vh, const __nv_bfloat16* __restrict__ vl,
    const unsigned char* __restrict__ mask,
    float* __restrict__ att,
    __nv_bfloat16* __restrict__ oh, __nv_bfloat16* __restrict__ ol)
{
    extern __shared__ __align__(128) char sm[];
    __shared__ int s_any;
    const uint32_t sbase = cvta_s(sm);
    const int tid = threadIdx.x;
    const int lane = tid & 31, w = tid >> 5;
    const int qt = blockIdx.x, bh = blockIdx.y;
    const int b = bh >> 4, h = bh & 15;
    const int q0 = qt * 16;
    const long base = (long)bh * SEQ * 64;
    const float scale = 1.0f / (8.0f + 1e-6f);
    float* Ss = (float*)(sm + SM_SS);

    auto fillKV = [&](const __nv_bfloat16* phi_, const __nv_bfloat16* plo_, int buf, int kt) {
#pragma unroll
        for (int i = 0; i < 4; i++) {
            const int idx = i * 256 + tid;
            const int arr = idx >> 9;
            const int wi = idx & 511;
            const int row = wi >> 3, seg = wi & 7;
            const __nv_bfloat16* g = (arr ? plo_ : phi_) + base + (long)(kt * 64 + row) * 64 + seg * 8;
            cp16(sbase + SM_KV + buf * 18432 + arr * 9216 + row * 144 + seg * 16, g);
        }
        CP_COMMIT();
    };

    {
        const int arr = tid >> 7;
        const int wi = tid & 127;
        const int row = wi >> 3, seg = wi & 7;
        const __nv_bfloat16* g = (arr ? ql : qh) + base + (long)(q0 + row) * 64 + seg * 8;
        cp16(sbase + (arr ? SM_QL : SM_QH) + row * 144 + seg * 16, g);
    }
    if (tid == 0) s_any = 0;
    fillKV(kh, kl, 0, 0);

    if (tid < 16 && mask[b * SEQ + q0 + tid]) s_any = 1;

    const int kt_max = (q0 + 15) >> 6;

    // ---- phase 1: scores ----
    uint32_t ah[4][4], al[4][4];
    for (int kt = 0; kt <= kt_max; kt++) {
        const int buf = kt & 1;
        if (kt < kt_max) {
            fillKV(kh, kl, buf ^ 1, kt + 1);
            asm volatile("cp.async.wait_group 1;" ::: "memory");
        } else {
            asm volatile("cp.async.wait_group 0;" ::: "memory");
        }
        __syncthreads();
        if (kt == 0) {
#pragma unroll
            for (int s = 0; s < 4; s++) {
                const uint32_t qa = sbase + (lane & 15) * 144 + s * 32 + (lane >> 4) * 16;
                ldsm4(ah[s], qa + SM_QH);
                ldsm4(al[s], qa + SM_QL);
            }
        }
        const uint32_t khb = sbase + SM_KV + buf * 18432;
        const int le = lane & 15;
        float c[4] = {0, 0, 0, 0};
#pragma unroll
        for (int s = 0; s < 4; s++) {
            uint32_t bhr[2], blr[2];
            const uint32_t ka = khb + (w * 8 + (le & 7)) * 144 + s * 32 + ((le >> 3) & 1) * 16;
            ldsm2(bhr, ka);
            ldsm2(blr, ka + 9216);
            mma_bf16(c, ah[s], bhr);
            mma_bf16(c, ah[s], blr);
            mma_bf16(c, al[s], bhr);
        }
        const int r = lane >> 2, col = kt * 64 + w * 8 + (lane & 3) * 2;
        float2 st0; st0.x = c[0] * scale; st0.y = c[1] * scale;
        float2 st1; st1.x = c[2] * scale; st1.y = c[3] * scale;
        *(float2*)(Ss + r * SSP + col) = st0;
        *(float2*)(Ss + (r + 8) * SSP + col) = st1;
        __syncthreads();
    }

    const int kt_end = s_any ? (SEQ / 64 - 1) : kt_max;

    fillKV(vh, vl, 0, 0);

    // ---- phase 2: softmax ----
    {
        const int r = tid >> 4, tc = tid & 15;
        const int qg = q0 + r;
        const int limit = qg;
        const bool rmask = mask[b * SEQ + qg] != 0;
        float* srow = Ss + r * SSP;

        float mx = -3.4e38f;
#pragma unroll 4
        for (int j = 0; j < 64; j++) {
            const int k = tc + (j << 4);
            if (k <= limit) mx = fmaxf(mx, srow[k]);
        }
#pragma unroll
        for (int off = 8; off; off >>= 1)
            mx = fmaxf(mx, __shfl_xor_sync(0xffffffffu, mx, off, 16));

        float l = 0.0f;
#pragma unroll 4
        for (int j = 0; j < 64; j++) {
            const int k = tc + (j << 4);
            if (k <= limit) {
                const float e = fast_exp(srow[k] - mx);
                srow[k] = e;
                l += e;
            }
        }
#pragma unroll
        for (int off = 8; off; off >>= 1)
            l += __shfl_xor_sync(0xffffffffu, l, off, 16);
        const float inv = 1.0f / l;
        const float invS = 1.0f / (float)SEQ;

        float* attrow = att + ((long)bh * SEQ + qg) * SEQ;
        __nv_bfloat16* phrow = (__nv_bfloat16*)(sm + SM_PH) + r * SSP;
        __nv_bfloat16* plrow = (__nv_bfloat16*)(sm + SM_PL) + r * SSP;
#pragma unroll 4
        for (int j = 0; j < 64; j++) {
            const int k = tc + (j << 4);
            float p;
            if (rmask)           p = invS;
            else if (k <= limit) p = srow[k] * inv;
            else                 p = 0.0f;
            attrow[k] = p;
            const __nv_bfloat16 hi = __float2bfloat16(p);
            phrow[k] = hi;
            plrow[k] = __float2bfloat16(p - __bfloat162float(hi));
        }
    }
    __syncthreads();

    // ---- phase 3: AV ----
    float o[4] = {0, 0, 0, 0};
    for (int kt = 0; kt <= kt_end; kt++) {
        const int buf = kt & 1;
        if (kt < kt_end) {
            fillKV(vh, vl, buf ^ 1, kt + 1);
            asm volatile("cp.async.wait_group 1;" ::: "memory");
        } else {
            asm volatile("cp.async.wait_group 0;" ::: "memory");
        }
        __syncthreads();
        const uint32_t vbh = sbase + SM_KV + buf * 18432;
#pragma unroll
        for (int s = 0; s < 4; s++) {
            uint32_t pa[4], pb[4], vvh[2], vvl[2];
            const uint32_t colb = (kt * 64 + s * 16) * 2 + (lane >> 4) * 16;
            const uint32_t prow = (lane & 15) * 2064;
            ldsm4(pa, sbase + SM_PH + prow + colb);
            ldsm4(pb, sbase + SM_PL + prow + colb);
            const uint32_t va = vbh + (s * 16 + (lane & 15)) * 144 + w * 16;
            ldsm2t(vvh, va);
            ldsm2t(vvl, va + 9216);
            mma_bf16(o, pa, vvh);
            mma_bf16(o, pa, vvl);
            mma_bf16(o, pb, vvh);
        }
        __syncthreads();
    }

    // epilogue: bf16 hi/lo direct to [M][1024]
    const int r = lane >> 2, dv = w * 8 + (lane & 3) * 2;
    const long off0 = ((long)(b * SEQ + q0 + r)) * 1024 + h * 64 + dv;
    const long off1 = ((long)(b * SEQ + q0 + r + 8)) * 1024 + h * 64 + dv;
    __nv_bfloat162 h2, l2;
    split2(o[0], o[1], h2, l2);
    *(__nv_bfloat162*)(oh + off0) = h2;
    *(__nv_bfloat162*)(ol + off0) = l2;
    split2(o[2], o[3], h2, l2);
    *(__nv_bfloat162*)(oh + off1) = h2;
    *(__nv_bfloat162*)(ol + off1) = l2;
}

// ---------------- layernorm (optionally emits bf16 hi/lo split) ----------------
template<bool SPLIT>
__global__ void __launch_bounds__(256) ln_kernel(
    const float* __restrict__ x, const float* __restrict__ gam,
    const float* __restrict__ bet, float* __restrict__ out,
    __nv_bfloat16* __restrict__ ohi, __nv_bfloat16* __restrict__ olo)
{
    __shared__ float red[256];
    const int row = blockIdx.x, tid = threadIdx.x;
    const float4 v = ((const float4*)x)[(long)row * 256 + tid];
    red[tid] = v.x + v.y + v.z + v.w;
    __syncthreads();
#pragma unroll
    for (int off = 128; off; off >>= 1) {
        if (tid < off) red[tid] += red[tid + off];
        __syncthreads();
    }
    const float mu = red[0] * (1.0f / 1024.0f);
    __syncthreads();
    const float dx = v.x - mu, dy = v.y - mu, dz = v.z - mu, dw = v.w - mu;
    red[tid] = dx * dx + dy * dy + dz * dz + dw * dw;
    __syncthreads();
#pragma unroll
    for (int off = 128; off; off >>= 1) {
        if (tid < off) red[tid] += red[tid + off];
        __syncthreads();
    }
    const float var = red[0] * (1.0f / 1024.0f);
    const float rs = rsqrtf(var + 1e-5f);
    const float4 g4 = ((const float4*)gam)[tid];
    const float4 b4 = ((const float4*)bet)[tid];
    float4 o;
    o.x = g4.x * dx * rs + b4.x;
    o.y = g4.y * dy * rs + b4.y;
    o.z = g4.z * dz * rs + b4.z;
    o.w = g4.w * dw * rs + b4.w;
    ((float4*)out)[(long)row * 256 + tid] = o;
    if (SPLIT) {
        const long i = (long)row * 256 + tid;
        __nv_bfloat162 hA, lA, hB, lB;
        split2(o.x, o.y, hA, lA);
        split2(o.z, o.w, hB, lB);
        ((__nv_bfloat162*)ohi)[i*2]   = hA;
        ((__nv_bfloat162*)ohi)[i*2+1] = hB;
        ((__nv_bfloat162*)olo)[i*2]   = lA;
        ((__nv_bfloat162*)olo)[i*2+1] = lB;
    }
}

// ---------------- launch ----------------
extern "C" void kernel_launch(void* const* d_in, const int* in_sizes, int n_in,
                              void* d_out, int out_size) {
    const float* Qin  = (const float*)d_in[0];
    const float* Kin  = (const float*)d_in[1];
    const float* Vin  = (const float*)d_in[2];
    const unsigned char* mask = (const unsigned char*)d_in[3];
    const float* W_q  = (const float*)d_in[4];
    const float* W_k  = (const float*)d_in[5];
    const float* W_v  = (const float*)d_in[6];
    const float* W_o  = (const float*)d_in[7];
    const float* w1   = (const float*)d_in[8];
    const float* b1   = (const float*)d_in[9];
    const float* w2   = (const float*)d_in[10];
    const float* b2   = (const float*)d_in[11];
    const float* ln_g = (const float*)d_in[12];
    const float* ln_b = (const float*)d_in[13];

    float *y_, *x_, *attfb_;
    cudaGetSymbolAddress((void**)&y_, g_y);
    cudaGetSymbolAddress((void**)&x_, g_x);
    cudaGetSymbolAddress((void**)&attfb_, g_att_fb);

    __nv_bfloat16 *ahi, *alo, *qh_, *ql_, *kh_, *kl_, *vh_, *vl_;
    __nv_bfloat16 *wqh, *wql, *wkh, *wkl, *wvh, *wvl, *woh, *wol, *w1h, *w1l, *w2h, *w2l;
    cudaGetSymbolAddress((void**)&ahi, g_ahi);
    cudaGetSymbolAddress((void**)&alo, g_alo);
    cudaGetSymbolAddress((void**)&qh_, g_qh); cudaGetSymbolAddress((void**)&ql_, g_ql);
    cudaGetSymbolAddress((void**)&kh_, g_kh); cudaGetSymbolAddress((void**)&kl_, g_kl);
    cudaGetSymbolAddress((void**)&vh_, g_vh); cudaGetSymbolAddress((void**)&vl_, g_vl);
    cudaGetSymbolAddress((void**)&wqh, g_wqh); cudaGetSymbolAddress((void**)&wql, g_wql);
    cudaGetSymbolAddress((void**)&wkh, g_wkh); cudaGetSymbolAddress((void**)&wkl, g_wkl);
    cudaGetSymbolAddress((void**)&wvh, g_wvh); cudaGetSymbolAddress((void**)&wvl, g_wvl);
    cudaGetSymbolAddress((void**)&woh, g_woh); cudaGetSymbolAddress((void**)&wol, g_wol);
    cudaGetSymbolAddress((void**)&w1h, g_w1h); cudaGetSymbolAddress((void**)&w1l, g_w1l);
    cudaGetSymbolAddress((void**)&w2h, g_w2h); cudaGetSymbolAddress((void**)&w2l, g_w2l);

    // alias free fp32 scratch as bf16 split storage for K/V input splits
    __nv_bfloat16* kinh = (__nv_bfloat16*)y_;
    __nv_bfloat16* kinl = kinh + OUT_MAIN;
    __nv_bfloat16* vinh = (__nv_bfloat16*)x_;
    __nv_bfloat16* vinl = vinh + OUT_MAIN;

    float* out = (float*)d_out;
    float* att = (out_size >= (int)(OUT_MAIN + OUT_ATT)) ? (out + OUT_MAIN) : attfb_;

    cudaFuncSetAttribute(mma_gemm<0>, cudaFuncAttributeMaxDynamicSharedMemorySize, GEMM_SMEM);
    cudaFuncSetAttribute(mma_gemm<1>, cudaFuncAttributeMaxDynamicSharedMemorySize, GEMM_SMEM);
    cudaFuncSetAttribute(mma_gemm<2>, cudaFuncAttributeMaxDynamicSharedMemorySize, GEMM_SMEM);
    cudaFuncSetAttribute(mma_gemm<3>, cudaFuncAttributeMaxDynamicSharedMemorySize, GEMM_SMEM);
    cudaFuncSetAttribute(attn2, cudaFuncAttributeMaxDynamicSharedMemorySize, ATTN_SMEM);

    // weight preps (batched)
    split_transpose4<<<dim3(32, 32, 4), dim3(32, 8)>>>(
        W_q, W_k, W_v, W_o, wqh, wql, wkh, wkl, wvh, wvl, woh, wol);
    splitmulti<<<dim3(DM * DM / 1024, 2), 256>>>(
        w1, w2, nullptr, w1h, w1l, w2h, w2l, nullptr, nullptr);

    // input splits (batched)
    splitmulti<<<dim3(MROWS * DM / 1024, 3), 256>>>(
        Qin, Kin, Vin, ahi, alo, kinh, kinl, vinh, vinl);

    const dim3 gG(8, 64), bG(256);
    mma_gemm<0><<<gG, bG, GEMM_SMEM>>>(ahi, alo, wqh, wql, nullptr, nullptr, nullptr, qh_, ql_);
    mma_gemm<0><<<gG, bG, GEMM_SMEM>>>(kinh, kinl, wkh, wkl, nullptr, nullptr, nullptr, kh_, kl_);
    mma_gemm<0><<<gG, bG, GEMM_SMEM>>>(vinh, vinl, wvh, wvl, nullptr, nullptr, nullptr, vh_, vl_);

    attn2<<<dim3(SEQ / 16, BB * NH), 256, ATTN_SMEM>>>(
        qh_, ql_, kh_, kl_, vh_, vl_, mask, att, ahi, alo);

    mma_gemm<1><<<gG, bG, GEMM_SMEM>>>(ahi, alo, woh, wol, y_, Qin, nullptr, nullptr, nullptr);
    ln_kernel<true><<<MROWS, 256>>>(y_, ln_g, ln_b, x_, kh_, kl_);
    mma_gemm<2><<<gG, bG, GEMM_SMEM>>>(kh_, kl_, w1h, w1l, nullptr, nullptr, b1, vh_, vl_);
    mma_gemm<3><<<gG, bG, GEMM_SMEM>>>(vh_, vl_, w2h, w2l, y_, x_, b2, nullptr, nullptr);
    ln_kernel<false><<<MROWS, 256>>>(y_, ln_g, ln_b, out, nullptr, nullptr);
}